// round 7
// baseline (speedup 1.0000x reference)
#include <cuda_runtime.h>
#include <cuda_bf16.h>
#include <math.h>
#include <stdint.h>

#define BB 4
#define SS 2048
#define DD 1024
#define HH 16
#define HDIM 64
#define MR (BB * SS)   // 8192

// ---- f32 scratch ----
__device__ float g_base[(size_t)MR * 3 * DD];     // [8192,3072]
__device__ float g_hidden[(size_t)MR * DD];       // [8192,1024]
__device__ float g_ctrlp[(size_t)MR * 128];       // padded ctrl [8192,128] (H*8)
__device__ float g_ys[(size_t)MR * DD];           // [8192,1024]
__device__ float g_mf[(size_t)BB * HH * HDIM * HDIM];
// ---- bf16 hi/lo scratch ----
__device__ __nv_bfloat16 g_xh[(size_t)MR * DD],  g_xl[(size_t)MR * DD];
__device__ __nv_bfloat16 g_ysh[(size_t)MR * DD], g_ysl[(size_t)MR * DD];
__device__ __nv_bfloat16 g_w1h[(size_t)3 * DD * DD], g_w1l[(size_t)3 * DD * DD]; // W_in^T [3072,1024]
__device__ __nv_bfloat16 g_wc1h[(size_t)DD * DD],    g_wc1l[(size_t)DD * DD];    // Wc1^T
__device__ __nv_bfloat16 g_woh[(size_t)DD * DD],     g_wol[(size_t)DD * DD];     // W_out^T

// ===========================================================================
// helpers
// ===========================================================================
__device__ __forceinline__ void split2(float a0, float a1,
                                       unsigned& hi, unsigned& lo) {
    // hi = {bf16(a1) << 16 | bf16(a0)}
    asm("cvt.rn.bf16x2.f32 %0, %1, %2;" : "=r"(hi) : "f"(a1), "f"(a0));
    float h0 = __uint_as_float(hi << 16);
    float h1 = __uint_as_float(hi & 0xffff0000u);
    float r0 = a0 - h0, r1 = a1 - h1;
    asm("cvt.rn.bf16x2.f32 %0, %1, %2;" : "=r"(lo) : "f"(r1), "f"(r0));
}

__device__ __forceinline__ void mma_bf16(float* c, const unsigned* a,
                                         unsigned b0, unsigned b1) {
    asm volatile(
        "mma.sync.aligned.m16n8k16.row.col.f32.bf16.bf16.f32 "
        "{%0,%1,%2,%3}, {%4,%5,%6,%7}, {%8,%9}, {%0,%1,%2,%3};"
        : "+f"(c[0]), "+f"(c[1]), "+f"(c[2]), "+f"(c[3])
        : "r"(a[0]), "r"(a[1]), "r"(a[2]), "r"(a[3]), "r"(b0), "r"(b1));
}

__device__ __forceinline__ void cpa16(uint32_t s, const void* g) {
    asm volatile("cp.async.ca.shared.global [%0], [%1], 16;"
                 :: "r"(s), "l"(g) : "memory");
}
__device__ __forceinline__ void cpa4(uint32_t s, const void* g) {
    asm volatile("cp.async.ca.shared.global [%0], [%1], 4;"
                 :: "r"(s), "l"(g) : "memory");
}
__device__ __forceinline__ void cpcommit() {
    asm volatile("cp.async.commit_group;" ::: "memory");
}
template <int N>
__device__ __forceinline__ void cpwait() {
    asm volatile("cp.async.wait_group %0;" :: "n"(N) : "memory");
}

// ===========================================================================
// split kernels
// ===========================================================================
__global__ __launch_bounds__(256) void split_rows(
    const float* __restrict__ in, __nv_bfloat16* __restrict__ hi,
    __nv_bfloat16* __restrict__ lo)
{
    size_t i = ((size_t)blockIdx.x * 256 + threadIdx.x) * 4;
    float4 v = *(const float4*)(in + i);
    unsigned h01, l01, h23, l23;
    split2(v.x, v.y, h01, l01);
    split2(v.z, v.w, h23, l23);
    *(uint2*)((char*)hi + i * 2) = make_uint2(h01, h23);
    *(uint2*)((char*)lo + i * 2) = make_uint2(l01, l23);
}

// W [K,N] f32 -> W^T hi/lo [N,K] bf16
__global__ __launch_bounds__(256) void splitT(
    const float* __restrict__ W, __nv_bfloat16* __restrict__ th,
    __nv_bfloat16* __restrict__ tl, int K, int N)
{
    __shared__ float t[32][33];
    int n0 = blockIdx.x * 32, k0 = blockIdx.y * 32;
    int tx = threadIdx.x, ty = threadIdx.y;   // (32, 8)
#pragma unroll
    for (int i = 0; i < 32; i += 8)
        t[ty + i][tx] = W[(size_t)(k0 + ty + i) * N + n0 + tx];
    __syncthreads();
#pragma unroll
    for (int i = 0; i < 32; i += 8) {
        int n = n0 + ty + i, kk = k0 + tx;
        float v = t[tx][ty + i];
        __nv_bfloat16 h = __float2bfloat16(v);
        float r = v - __bfloat162float(h);
        th[(size_t)n * K + kk] = h;
        tl[(size_t)n * K + kk] = __float2bfloat16(r);
    }
}

// ===========================================================================
// Fast GEMM: C[M,N] = act(A @ W^T + bias), A as (Ah,Al) [M,K] bf16,
// W^T as (Bh,Bl) [N,K] bf16. Block 128x128, TBK=16, 4-stage cp.async.
// smem per stage: 4 planes (Ah,Al,Bh,Bl), each 128 rows x 12 u32 (stride-12
// padding dealiases banks; 16B chunks contiguous for cp.async).
// 256 thr, 8 warps (wm 0-3, wn 0-1), warp tile 32x64, bf16x3 mma.
// ===========================================================================
#define FPLANE 1536                 // u32 per plane
#define FSTAGE (4 * FPLANE)         // u32 per stage (24KB)
#define FSMEM  (4 * FSTAGE * 4)     // bytes (96KB)

__global__ __launch_bounds__(256) void gemm_fast(
    const __nv_bfloat16* __restrict__ Ah, const __nv_bfloat16* __restrict__ Al,
    const __nv_bfloat16* __restrict__ Bh, const __nv_bfloat16* __restrict__ Bl,
    const float* __restrict__ bias, float* __restrict__ C,
    int M, int N, int K, int act)
{
    extern __shared__ __align__(16) uint32_t sm[];

    int tid  = threadIdx.x;
    int lane = tid & 31;
    int warp = tid >> 5;
    int wm = warp >> 1, wn = warp & 1;
    int bm = blockIdx.y * 128;
    int bn = blockIdx.x * 128;

    // cp.async mapping: row = tid>>1 (0..127), chunk = tid&1 (each 16B = 8 bf16)
    int row = tid >> 1, ch = tid & 1;
    const __nv_bfloat16* gah = Ah + (size_t)(bm + row) * K + ch * 8;
    const __nv_bfloat16* gal = Al + (size_t)(bm + row) * K + ch * 8;
    const __nv_bfloat16* gbh = Bh + (size_t)(bn + row) * K + ch * 8;
    const __nv_bfloat16* gbl = Bl + (size_t)(bn + row) * K + ch * 8;
    uint32_t smem0 = (uint32_t)__cvta_generic_to_shared(sm);
    uint32_t dstoff = (row * 12 + ch * 4) * 4;   // bytes within plane

    // fragment indices
    int fg = lane >> 2, ft = lane & 3;
    int idxA[2][2];
#pragma unroll
    for (int i = 0; i < 2; i++)
#pragma unroll
        for (int d = 0; d < 2; d++)
            idxA[i][d] = (wm * 32 + i * 16 + d * 8 + fg) * 12 + ft;
    int idxB[8];
#pragma unroll
    for (int j = 0; j < 8; j++)
        idxB[j] = (wn * 64 + j * 8 + fg) * 12 + ft;

    float acc[2][8][4];
#pragma unroll
    for (int i = 0; i < 2; i++)
#pragma unroll
        for (int j = 0; j < 8; j++)
#pragma unroll
            for (int l = 0; l < 4; l++) acc[i][j][l] = 0.f;

    int nk = K / 16;  // 64

    // prologue: stages 0..2
#pragma unroll
    for (int p = 0; p < 3; p++) {
        uint32_t sb = smem0 + p * (FSTAGE * 4);
        int k0 = p * 16;
        cpa16(sb + dstoff,                      gah + k0);
        cpa16(sb + FPLANE * 4 + dstoff,         gal + k0);
        cpa16(sb + 2 * FPLANE * 4 + dstoff,     gbh + k0);
        cpa16(sb + 3 * FPLANE * 4 + dstoff,     gbl + k0);
        cpcommit();
    }

    for (int it = 0; it < nk; it++) {
        cpwait<2>();
        __syncthreads();   // stage it fully visible; prev compute done

        if (it + 3 < nk) {
            uint32_t sb = smem0 + ((it + 3) & 3) * (FSTAGE * 4);
            int k0 = (it + 3) * 16;
            cpa16(sb + dstoff,                  gah + k0);
            cpa16(sb + FPLANE * 4 + dstoff,     gal + k0);
            cpa16(sb + 2 * FPLANE * 4 + dstoff, gbh + k0);
            cpa16(sb + 3 * FPLANE * 4 + dstoff, gbl + k0);
        }
        cpcommit();

        const uint32_t* Ab = sm + (it & 3) * FSTAGE;
        const uint32_t* Alp = Ab + FPLANE;
        const uint32_t* Bb = Ab + 2 * FPLANE;
        const uint32_t* Blp = Ab + 3 * FPLANE;

        unsigned ahf[2][4], alf[2][4];
#pragma unroll
        for (int i = 0; i < 2; i++) {
            int b0 = idxA[i][0], b1 = idxA[i][1];
            ahf[i][0] = Ab[b0];     ahf[i][1] = Ab[b1];
            ahf[i][2] = Ab[b0 + 4]; ahf[i][3] = Ab[b1 + 4];
            alf[i][0] = Alp[b0];     alf[i][1] = Alp[b1];
            alf[i][2] = Alp[b0 + 4]; alf[i][3] = Alp[b1 + 4];
        }
#pragma unroll
        for (int j = 0; j < 8; j++) {
            unsigned bh0 = Bb[idxB[j]],  bh1 = Bb[idxB[j] + 4];
            unsigned bl0 = Blp[idxB[j]], bl1 = Blp[idxB[j] + 4];
            mma_bf16(acc[0][j], ahf[0], bh0, bh1);
            mma_bf16(acc[1][j], ahf[1], bh0, bh1);
            mma_bf16(acc[0][j], ahf[0], bl0, bl1);
            mma_bf16(acc[1][j], ahf[1], bl0, bl1);
            mma_bf16(acc[0][j], alf[0], bh0, bh1);
            mma_bf16(acc[1][j], alf[1], bh0, bh1);
        }
    }

    // epilogue
#pragma unroll
    for (int i = 0; i < 2; i++) {
        int orow = bm + wm * 32 + i * 16 + fg;
#pragma unroll
        for (int j = 0; j < 8; j++) {
            int col = bn + wn * 64 + j * 8 + ft * 2;
            float b0 = bias[col], b1 = bias[col + 1];
            float v0 = acc[i][j][0] + b0;
            float v1 = acc[i][j][1] + b1;
            float v2 = acc[i][j][2] + b0;
            float v3 = acc[i][j][3] + b1;
            if (act == 1) {
                v0 = v0 / (1.f + __expf(-v0));
                v1 = v1 / (1.f + __expf(-v1));
                v2 = v2 / (1.f + __expf(-v2));
                v3 = v3 / (1.f + __expf(-v3));
            }
            *(float2*)&C[(size_t)orow * N + col] = make_float2(v0, v1);
            *(float2*)&C[(size_t)(orow + 8) * N + col] = make_float2(v2, v3);
        }
    }
}

// ===========================================================================
// Legacy bf16x3 GEMM for the small ctrl GEMM (N=80), stores PADDED:
// output col j -> C[row*ldc + (j/5)*8 + j%5]
// ===========================================================================
#define TBM 128
#define TBN 128
#define TBK 16
#define XSTR 12
#define PLANE (TBM * XSTR)

__global__ __launch_bounds__(256) void gemm_ctrl(
    const float* __restrict__ A, const float* __restrict__ B,
    const float* __restrict__ bias, float* __restrict__ C,
    int M, int N, int K, int ldc)
{
    __shared__ __align__(16) unsigned As[2][2 * PLANE];
    __shared__ __align__(16) unsigned Bs[2][2 * PLANE];

    int tid  = threadIdx.x;
    int lane = tid & 31;
    int warp = tid >> 5;
    int wm = warp >> 1, wn = warp & 1;
    int bm = blockIdx.y * TBM;
    int bn = 0;

    int arow = tid >> 1, ah = tid & 1;
    const float* Aptr = A + (size_t)(bm + arow) * K + ah * 8;
    int xa = (arow & 3) ^ ((arow >> 3) & 3);
    int ast_base = arow * XSTR + 4 * ah;
    int bnn = tid & 127, bh2 = tid >> 7;
    int gcol = bn + bnn;
    int xb = (bnn & 3) ^ ((bnn >> 3) & 3);
    int bst_base = bnn * XSTR + 4 * bh2;

    int fg = lane >> 2, ft = lane & 3;
    int idxA[2][2];
#pragma unroll
    for (int i = 0; i < 2; i++)
#pragma unroll
        for (int d = 0; d < 2; d++) {
            int row = wm * 32 + i * 16 + d * 8 + fg;
            idxA[i][d] = row * XSTR + (ft ^ (row & 3) ^ ((row >> 3) & 3));
        }
    int idxB[8];
#pragma unroll
    for (int j = 0; j < 8; j++) {
        int n = wn * 64 + j * 8 + fg;
        idxB[j] = n * XSTR + (ft ^ (n & 3) ^ ((n >> 3) & 3));
    }

    float acc[2][8][4];
#pragma unroll
    for (int i = 0; i < 2; i++)
#pragma unroll
        for (int j = 0; j < 8; j++)
#pragma unroll
            for (int l = 0; l < 4; l++) acc[i][j][l] = 0.f;

    {
        float4 f0 = *(const float4*)Aptr;
        float4 f1 = *(const float4*)(Aptr + 4);
        unsigned hi, lo;
        split2(f0.x, f0.y, hi, lo);
        As[0][ast_base + (0 ^ xa)] = hi; As[0][PLANE + ast_base + (0 ^ xa)] = lo;
        split2(f0.z, f0.w, hi, lo);
        As[0][ast_base + (1 ^ xa)] = hi; As[0][PLANE + ast_base + (1 ^ xa)] = lo;
        split2(f1.x, f1.y, hi, lo);
        As[0][ast_base + (2 ^ xa)] = hi; As[0][PLANE + ast_base + (2 ^ xa)] = lo;
        split2(f1.z, f1.w, hi, lo);
        As[0][ast_base + (3 ^ xa)] = hi; As[0][PLANE + ast_base + (3 ^ xa)] = lo;
#pragma unroll
        for (int i = 0; i < 4; i++) {
            int k = 8 * bh2 + 2 * i;
            float b0 = (gcol < N) ? B[(size_t)k * N + gcol] : 0.f;
            float b1 = (gcol < N) ? B[(size_t)(k + 1) * N + gcol] : 0.f;
            split2(b0, b1, hi, lo);
            Bs[0][bst_base + (i ^ xb)] = hi;
            Bs[0][PLANE + bst_base + (i ^ xb)] = lo;
        }
    }
    __syncthreads();

    int iters = K / TBK;
    for (int it = 1; it <= iters; it++) {
        bool has = (it < iters);
        float4 f0, f1;
        float bg[8];
        if (has) {
            int k0 = it * TBK;
            f0 = *(const float4*)(Aptr + k0);
            f1 = *(const float4*)(Aptr + k0 + 4);
#pragma unroll
            for (int i = 0; i < 4; i++) {
                int k = k0 + 8 * bh2 + 2 * i;
                bg[2 * i]     = (gcol < N) ? B[(size_t)k * N + gcol] : 0.f;
                bg[2 * i + 1] = (gcol < N) ? B[(size_t)(k + 1) * N + gcol] : 0.f;
            }
        }
        {
            const unsigned* Ab = As[(it - 1) & 1];
            const unsigned* Bb = Bs[(it - 1) & 1];
            unsigned ahf[2][4], alf[2][4];
#pragma unroll
            for (int i = 0; i < 2; i++) {
                ahf[i][0] = Ab[idxA[i][0]];
                ahf[i][1] = Ab[idxA[i][1]];
                ahf[i][2] = Ab[idxA[i][0] + 4];
                ahf[i][3] = Ab[idxA[i][1] + 4];
                alf[i][0] = Ab[PLANE + idxA[i][0]];
                alf[i][1] = Ab[PLANE + idxA[i][1]];
                alf[i][2] = Ab[PLANE + idxA[i][0] + 4];
                alf[i][3] = Ab[PLANE + idxA[i][1] + 4];
            }
#pragma unroll
            for (int j = 0; j < 8; j++) {
                unsigned bh0 = Bb[idxB[j]];
                unsigned bh1 = Bb[idxB[j] + 4];
                unsigned bl0 = Bb[PLANE + idxB[j]];
                unsigned bl1 = Bb[PLANE + idxB[j] + 4];
                mma_bf16(acc[0][j], ahf[0], bh0, bh1);
                mma_bf16(acc[1][j], ahf[1], bh0, bh1);
                mma_bf16(acc[0][j], ahf[0], bl0, bl1);
                mma_bf16(acc[1][j], ahf[1], bl0, bl1);
                mma_bf16(acc[0][j], alf[0], bh0, bh1);
                mma_bf16(acc[1][j], alf[1], bh0, bh1);
            }
        }
        if (has) {
            int buf = it & 1;
            unsigned hi, lo;
            split2(f0.x, f0.y, hi, lo);
            As[buf][ast_base + (0 ^ xa)] = hi; As[buf][PLANE + ast_base + (0 ^ xa)] = lo;
            split2(f0.z, f0.w, hi, lo);
            As[buf][ast_base + (1 ^ xa)] = hi; As[buf][PLANE + ast_base + (1 ^ xa)] = lo;
            split2(f1.x, f1.y, hi, lo);
            As[buf][ast_base + (2 ^ xa)] = hi; As[buf][PLANE + ast_base + (2 ^ xa)] = lo;
            split2(f1.z, f1.w, hi, lo);
            As[buf][ast_base + (3 ^ xa)] = hi; As[buf][PLANE + ast_base + (3 ^ xa)] = lo;
#pragma unroll
            for (int i = 0; i < 4; i++) {
                split2(bg[2 * i], bg[2 * i + 1], hi, lo);
                Bs[buf][bst_base + (i ^ xb)] = hi;
                Bs[buf][PLANE + bst_base + (i ^ xb)] = lo;
            }
        }
        __syncthreads();
    }

    // padded-store epilogue
#pragma unroll
    for (int i = 0; i < 2; i++) {
        int row = bm + wm * 32 + i * 16 + fg;
#pragma unroll
        for (int j = 0; j < 8; j++) {
            int col = bn + wn * 64 + j * 8 + ft * 2;
            if (col < N) {
                float v0 = acc[i][j][0] + bias[col];
                float v2 = acc[i][j][2] + bias[col];
                int p0 = (col / 5) * 8 + col % 5;
                C[(size_t)row * ldc + p0] = v0;
                C[(size_t)(row + 8) * ldc + p0] = v2;
                if (col + 1 < N) {
                    float v1 = acc[i][j][1] + bias[col + 1];
                    float v3 = acc[i][j][3] + bias[col + 1];
                    int p1 = ((col + 1) / 5) * 8 + (col + 1) % 5;
                    C[(size_t)row * ldc + p1] = v1;
                    C[(size_t)(row + 8) * ldc + p1] = v3;
                }
            }
        }
    }
}

// ===========================================================================
// Barrier-free scan. 128 blocks: (b*16+h)*2+half; 128 threads:
// r=(tid>>2)+half*32, g=tid&3. Per-WARP cp.async slices (6 deep):
// slice = k[64] q[64] v[8] c[8] floats; wait_group + __syncwarp only.
// ===========================================================================
#define SCD 6

__global__ __launch_bounds__(128) void scan_kernel(
    const float* __restrict__ base,    // [B,S,H,3,HD]
    const float* __restrict__ ctrlp,   // [B,S,H*8] padded
    const float* __restrict__ memory0,
    float* __restrict__ ys,
    float* __restrict__ mfinal)
{
    __shared__ __align__(16) float sl[SCD][4][144];

    int bh   = blockIdx.x >> 1;
    int half = blockIdx.x & 1;
    int b = bh >> 4, h = bh & 15;
    int tid = threadIdx.x, lane = tid & 31, w = tid >> 5;
    int r = (tid >> 2) + half * 32;
    int g = tid & 3;
    int rloc = (tid >> 2) & 7;

    float m[16];
    {
        const float* M0 = memory0 + (((size_t)bh * HDIM + r) * HDIM + g * 16);
#pragma unroll
        for (int jj = 0; jj < 16; jj++) m[jj] = M0[jj];
    }

    const float* bsrc = base + ((size_t)b * SS * HH + h) * 192;   // +s*3072
    const float* csrc = ctrlp + (size_t)b * SS * 128 + h * 8;     // +s*128
    float* yptr = ys + (size_t)b * SS * DD + h * HDIM + r;
    int vbase = 64 + half * 32 + 8 * w;   // this warp's v rows

    uint32_t slw_addr[SCD];
#pragma unroll
    for (int d = 0; d < SCD; d++)
        slw_addr[d] = (uint32_t)__cvta_generic_to_shared(&sl[d][w][0]);

#define SCAN_ISSUE(st) do {                                                  \
        uint32_t sb_ = slw_addr[(st) % SCD];                                 \
        const float* bp_ = bsrc + (size_t)(st) * 3072;                       \
        const float* cp_ = csrc + (size_t)(st) * 128;                        \
        if (lane < 16) cpa16(sb_ + lane * 16, bp_ + lane * 4);               \
        else cpa16(sb_ + 256 + (lane - 16) * 16, bp_ + 128 + (lane - 16) * 4); \
        if (lane == 0) cpa16(sb_ + 512, bp_ + vbase);                        \
        else if (lane == 1) cpa16(sb_ + 528, bp_ + vbase + 4);               \
        else if (lane == 2) cpa16(sb_ + 544, cp_);                           \
        else if (lane == 3) cpa16(sb_ + 560, cp_ + 4);                       \
        cpcommit();                                                          \
    } while (0)

#pragma unroll
    for (int p = 0; p < SCD - 1; p++) SCAN_ISSUE(p);

    int slot = 0;
    for (int s = 0; s < SS; s++) {
        if (s + SCD - 1 < SS) SCAN_ISSUE(s + SCD - 1);
        else cpcommit();
        cpwait<SCD - 1>();
        __syncwarp();

        const float* sw = &sl[slot][w][0];
        if (++slot == SCD) slot = 0;

        float kr[16], qr[16];
#pragma unroll
        for (int i = 0; i < 4; i++) {
            *(float4*)&kr[i * 4] = *(const float4*)&sw[g * 16 + i * 4];
            *(float4*)&qr[i * 4] = *(const float4*)&sw[64 + g * 16 + i * 4];
        }
        float vv = sw[128 + rloc];
        float c0 = sw[136], c1 = sw[137], c2 = sw[138];
        float eta   = 1.f / (1.f + __expf(-sw[139]));
        float alpha = 1.f / (1.f + __expf(-sw[140]));

        float dq0 = 0.f, dq1 = 0.f, dk0 = 0.f, dk1 = 0.f;
#pragma unroll
        for (int jj = 0; jj < 16; jj += 2) {
            dq0 += m[jj] * qr[jj];
            dq1 += m[jj + 1] * qr[jj + 1];
            dk0 += m[jj] * kr[jj];
            dk1 += m[jj + 1] * kr[jj + 1];
        }
        float dq = dq0 + dq1, dk = dk0 + dk1;
        dq += __shfl_xor_sync(0xffffffffu, dq, 1);
        dq += __shfl_xor_sync(0xffffffffu, dq, 2);
        dk += __shfl_xor_sync(0xffffffffu, dk, 1);
        dk += __shfl_xor_sync(0xffffffffu, dk, 2);

        float err = c0 * dk - c1 * vv;
        if (g == 0) yptr[(size_t)s * DD] = c2 * dq;

        float ekc = eta * err * c0;
#pragma unroll
        for (int jj = 0; jj < 16; jj++)
            m[jj] = alpha * m[jj] + ekc * kr[jj];
    }

    float* MF = mfinal + (((size_t)bh * HDIM + r) * HDIM + g * 16);
#pragma unroll
    for (int jj = 0; jj < 16; jj++) MF[jj] = m[jj];
}

// ===========================================================================
extern "C" void kernel_launch(void* const* d_in, const int* in_sizes, int n_in,
                              void* d_out, int out_size)
{
    (void)in_sizes; (void)n_in;
    const float* x       = (const float*)d_in[0];
    const float* memory0 = (const float*)d_in[1];
    const float* W_in    = (const float*)d_in[2];
    const float* b_in    = (const float*)d_in[3];
    const float* Wc1     = (const float*)d_in[4];
    const float* bc1     = (const float*)d_in[5];
    const float* Wc2     = (const float*)d_in[6];
    const float* bc2     = (const float*)d_in[7];
    const float* W_out   = (const float*)d_in[8];
    const float* b_out   = (const float*)d_in[9];

    float* out = (float*)d_out;

    float *base, *hidden, *ctrlp, *ys, *mf_scratch;
    cudaGetSymbolAddress((void**)&base,       g_base);
    cudaGetSymbolAddress((void**)&hidden,     g_hidden);
    cudaGetSymbolAddress((void**)&ctrlp,      g_ctrlp);
    cudaGetSymbolAddress((void**)&ys,         g_ys);
    cudaGetSymbolAddress((void**)&mf_scratch, g_mf);

    __nv_bfloat16 *xh, *xl, *ysh, *ysl, *w1h, *w1l, *wc1h, *wc1l, *woh, *wol;
    cudaGetSymbolAddress((void**)&xh,  g_xh);   cudaGetSymbolAddress((void**)&xl,  g_xl);
    cudaGetSymbolAddress((void**)&ysh, g_ysh);  cudaGetSymbolAddress((void**)&ysl, g_ysl);
    cudaGetSymbolAddress((void**)&w1h, g_w1h);  cudaGetSymbolAddress((void**)&w1l, g_w1l);
    cudaGetSymbolAddress((void**)&wc1h, g_wc1h); cudaGetSymbolAddress((void**)&wc1l, g_wc1l);
    cudaGetSymbolAddress((void**)&woh, g_woh);  cudaGetSymbolAddress((void**)&wol, g_wol);

    const size_t OUT_ELEMS = (size_t)MR * DD;
    const size_t MF_ELEMS  = (size_t)BB * HH * HDIM * HDIM;
    float* mfinal = ((size_t)out_size >= OUT_ELEMS + MF_ELEMS)
                        ? (out + OUT_ELEMS) : mf_scratch;

    cudaFuncSetAttribute(gemm_fast, cudaFuncAttributeMaxDynamicSharedMemorySize,
                         FSMEM);

    // pre-split inputs / weights
    split_rows<<<MR * DD / 1024, 256>>>(x, xh, xl);
    splitT<<<dim3(3 * DD / 32, DD / 32), dim3(32, 8)>>>(W_in, w1h, w1l, DD, 3 * DD);
    splitT<<<dim3(DD / 32, DD / 32), dim3(32, 8)>>>(Wc1, wc1h, wc1l, DD, DD);
    splitT<<<dim3(DD / 32, DD / 32), dim3(32, 8)>>>(W_out, woh, wol, DD, DD);

    // base = x @ W_in + b_in
    gemm_fast<<<dim3(3 * DD / 128, MR / 128), 256, FSMEM>>>(
        xh, xl, w1h, w1l, b_in, base, MR, 3 * DD, DD, 0);
    // hidden = silu(x @ Wc1 + bc1)
    gemm_fast<<<dim3(DD / 128, MR / 128), 256, FSMEM>>>(
        xh, xl, wc1h, wc1l, bc1, hidden, MR, DD, DD, 1);
    // ctrl (padded stride 8) = hidden @ Wc2 + bc2
    gemm_ctrl<<<dim3(1, MR / 128), 256>>>(
        hidden, Wc2, bc2, ctrlp, MR, 5 * HH, DD, 128);
    // sequential scan
    scan_kernel<<<BB * HH * 2, 128>>>(base, ctrlp, memory0, ys, mfinal);
    // out = ys @ W_out + b_out
    split_rows<<<MR * DD / 1024, 256>>>(ys, ysh, ysl);
    gemm_fast<<<dim3(DD / 128, MR / 128), 256, FSMEM>>>(
        ysh, ysl, woh, wol, b_out, out, MR, DD, DD, 0);
}

// round 8
// speedup vs baseline: 1.1897x; 1.1897x over previous
#include <cuda_runtime.h>
#include <cuda_bf16.h>
#include <math.h>
#include <stdint.h>

#define BB 4
#define SS 2048
#define DD 1024
#define HH 16
#define HDIM 64
#define MR (BB * SS)   // 8192

// ---- f32 scratch ----
__device__ float g_base[(size_t)MR * 3 * DD];     // [8192,3072]
__device__ float g_hidden[(size_t)MR * DD];       // [8192,1024]
__device__ float g_ctrl[(size_t)MR * 80];         // [8192,80]
__device__ float g_ys[(size_t)MR * DD];           // [8192,1024]
__device__ float g_mf[(size_t)BB * HH * HDIM * HDIM];
// ---- bf16 hi/lo scratch ----
__device__ __nv_bfloat16 g_xh[(size_t)MR * DD],  g_xl[(size_t)MR * DD];
__device__ __nv_bfloat16 g_ysh[(size_t)MR * DD], g_ysl[(size_t)MR * DD];
__device__ __nv_bfloat16 g_w1h[(size_t)3 * DD * DD], g_w1l[(size_t)3 * DD * DD]; // W_in^T
__device__ __nv_bfloat16 g_wc1h[(size_t)DD * DD],    g_wc1l[(size_t)DD * DD];    // Wc1^T
__device__ __nv_bfloat16 g_woh[(size_t)DD * DD],     g_wol[(size_t)DD * DD];     // W_out^T

// ===========================================================================
// helpers
// ===========================================================================
__device__ __forceinline__ void split2(float a0, float a1,
                                       unsigned& hi, unsigned& lo) {
    asm("cvt.rn.bf16x2.f32 %0, %1, %2;" : "=r"(hi) : "f"(a1), "f"(a0));
    float h0 = __uint_as_float(hi << 16);
    float h1 = __uint_as_float(hi & 0xffff0000u);
    float r0 = a0 - h0, r1 = a1 - h1;
    asm("cvt.rn.bf16x2.f32 %0, %1, %2;" : "=r"(lo) : "f"(r1), "f"(r0));
}

__device__ __forceinline__ void mma_bf16(float* c, const unsigned* a,
                                         unsigned b0, unsigned b1) {
    asm volatile(
        "mma.sync.aligned.m16n8k16.row.col.f32.bf16.bf16.f32 "
        "{%0,%1,%2,%3}, {%4,%5,%6,%7}, {%8,%9}, {%0,%1,%2,%3};"
        : "+f"(c[0]), "+f"(c[1]), "+f"(c[2]), "+f"(c[3])
        : "r"(a[0]), "r"(a[1]), "r"(a[2]), "r"(a[3]), "r"(b0), "r"(b1));
}

__device__ __forceinline__ void cpa16(uint32_t s, const void* g) {
    asm volatile("cp.async.ca.shared.global [%0], [%1], 16;"
                 :: "r"(s), "l"(g) : "memory");
}
__device__ __forceinline__ void cpa4(uint32_t s, const void* g) {
    asm volatile("cp.async.ca.shared.global [%0], [%1], 4;"
                 :: "r"(s), "l"(g) : "memory");
}
__device__ __forceinline__ void cpcommit() {
    asm volatile("cp.async.commit_group;" ::: "memory");
}
template <int N>
__device__ __forceinline__ void cpwait() {
    asm volatile("cp.async.wait_group %0;" :: "n"(N) : "memory");
}

// ===========================================================================
// split kernels
// ===========================================================================
__global__ __launch_bounds__(256) void split_rows(
    const float* __restrict__ in, __nv_bfloat16* __restrict__ hi,
    __nv_bfloat16* __restrict__ lo)
{
    size_t i = ((size_t)blockIdx.x * 256 + threadIdx.x) * 4;
    float4 v = *(const float4*)(in + i);
    unsigned h01, l01, h23, l23;
    split2(v.x, v.y, h01, l01);
    split2(v.z, v.w, h23, l23);
    *(uint2*)((char*)hi + i * 2) = make_uint2(h01, h23);
    *(uint2*)((char*)lo + i * 2) = make_uint2(l01, l23);
}

// W [K,N] f32 -> W^T hi/lo [N,K] bf16
__global__ __launch_bounds__(256) void splitT(
    const float* __restrict__ W, __nv_bfloat16* __restrict__ th,
    __nv_bfloat16* __restrict__ tl, int K, int N)
{
    __shared__ float t[32][33];
    int n0 = blockIdx.x * 32, k0 = blockIdx.y * 32;
    int tx = threadIdx.x, ty = threadIdx.y;   // (32, 8)
#pragma unroll
    for (int i = 0; i < 32; i += 8)
        t[ty + i][tx] = W[(size_t)(k0 + ty + i) * N + n0 + tx];
    __syncthreads();
#pragma unroll
    for (int i = 0; i < 32; i += 8) {
        int n = n0 + ty + i, kk = k0 + tx;
        float v = t[tx][ty + i];
        __nv_bfloat16 h = __float2bfloat16(v);
        float r = v - __bfloat162float(h);
        th[(size_t)n * K + kk] = h;
        tl[(size_t)n * K + kk] = __float2bfloat16(r);
    }
}

// ===========================================================================
// gemm_fast v2: C = act(A @ W^T + bias). A (Ah,Al) [M,K] bf16, W^T (Bh,Bl)
// [N,K] bf16. Block 128x128, K-chunk 32, 3-stage cp.async pipeline.
// Stage = 4 planes (Ah,Al,Bh,Bl), each 128 rows x 16 u32 (32 bf16), with
// chunk swizzle: 16B chunk c of row r stored at (c ^ ((r>>1)&3)).
//  -> fragment LDS fully bank-conflict-free; cp.async writes deg<=2.
// 256 thr, 8 warps (wm 0-3, wn 0-1), warp tile 32x64, bf16x3 mma.
// ===========================================================================
#define V2PLANE 2048                  // u32 per plane (8KB)
#define V2STAGE (4 * V2PLANE)         // u32 per stage (32KB)
#define V2SMEM  (3 * V2STAGE * 4)     // 98304 bytes

__global__ __launch_bounds__(256) void gemm_fast(
    const __nv_bfloat16* __restrict__ Ah, const __nv_bfloat16* __restrict__ Al,
    const __nv_bfloat16* __restrict__ Bh, const __nv_bfloat16* __restrict__ Bl,
    const float* __restrict__ bias, float* __restrict__ C,
    int M, int N, int K, int act)
{
    extern __shared__ __align__(16) uint32_t sm[];

    int tid  = threadIdx.x;
    int lane = tid & 31;
    int warp = tid >> 5;
    int wm = warp >> 1, wn = warp & 1;
    int bm = blockIdx.y * 128;
    int bn = blockIdx.x * 128;

    // cp.async mapping: row = tid>>1, chunk pair = {2*(tid&1), 2*(tid&1)+1}
    int row = tid >> 1;
    int cp0 = (tid & 1) * 2;
    int swr = ((row >> 1) & 3) << 2;                        // u32 units
    uint32_t dst0 = (uint32_t)(row * 16 + (((cp0 + 0) << 2) ^ swr)) * 4; // bytes
    uint32_t dst1 = (uint32_t)(row * 16 + (((cp0 + 1) << 2) ^ swr)) * 4;
    const __nv_bfloat16* gah = Ah + (size_t)(bm + row) * K + cp0 * 8;
    const __nv_bfloat16* gal = Al + (size_t)(bm + row) * K + cp0 * 8;
    const __nv_bfloat16* gbh = Bh + (size_t)(bn + row) * K + cp0 * 8;
    const __nv_bfloat16* gbl = Bl + (size_t)(bn + row) * K + cp0 * 8;
    uint32_t smem0 = (uint32_t)__cvta_generic_to_shared(sm);

    // fragment bases: addr_u32 = base + ((c<<2) ^ sw), c = 2*ks + half
    int fg = lane >> 2, ft = lane & 3;
    int baseA[2][2], swA[2][2];
#pragma unroll
    for (int i = 0; i < 2; i++)
#pragma unroll
        for (int d = 0; d < 2; d++) {
            int r_ = wm * 32 + i * 16 + d * 8 + fg;
            baseA[i][d] = r_ * 16 + ft;
            swA[i][d] = ((r_ >> 1) & 3) << 2;
        }
    int baseB[8], swB[8];
#pragma unroll
    for (int j = 0; j < 8; j++) {
        int n_ = wn * 64 + j * 8 + fg;
        baseB[j] = n_ * 16 + ft;
        swB[j] = ((n_ >> 1) & 3) << 2;
    }

    float acc[2][8][4];
#pragma unroll
    for (int i = 0; i < 2; i++)
#pragma unroll
        for (int j = 0; j < 8; j++)
#pragma unroll
            for (int l = 0; l < 4; l++) acc[i][j][l] = 0.f;

    int nk = K / 32;  // 32

#define V2_ISSUE(stage, slot) do {                                    \
        uint32_t sb_ = smem0 + (uint32_t)(slot) * (V2STAGE * 4);      \
        int k0_ = (stage) * 32;                                       \
        cpa16(sb_ + dst0,             gah + k0_);                     \
        cpa16(sb_ + dst1,             gah + k0_ + 8);                 \
        cpa16(sb_ + V2PLANE * 4 + dst0, gal + k0_);                   \
        cpa16(sb_ + V2PLANE * 4 + dst1, gal + k0_ + 8);               \
        cpa16(sb_ + 2 * V2PLANE * 4 + dst0, gbh + k0_);               \
        cpa16(sb_ + 2 * V2PLANE * 4 + dst1, gbh + k0_ + 8);           \
        cpa16(sb_ + 3 * V2PLANE * 4 + dst0, gbl + k0_);               \
        cpa16(sb_ + 3 * V2PLANE * 4 + dst1, gbl + k0_ + 8);           \
        cpcommit();                                                   \
    } while (0)

    V2_ISSUE(0, 0);
    V2_ISSUE(1, 1);

    int slot = 0;
    for (int it = 0; it < nk; it++) {
        cpwait<1>();
        __syncthreads();

        if (it + 2 < nk) {
            int ns = slot + 2; if (ns >= 3) ns -= 3;
            V2_ISSUE(it + 2, ns);
        } else {
            cpcommit();
        }

        const uint32_t* St  = sm + slot * V2STAGE;
        const uint32_t* Alp = St + V2PLANE;
        const uint32_t* Bhp = St + 2 * V2PLANE;
        const uint32_t* Blp = St + 3 * V2PLANE;

#pragma unroll
        for (int ks = 0; ks < 2; ks++) {
            unsigned ahf[2][4], alf[2][4];
#pragma unroll
            for (int i = 0; i < 2; i++) {
                int a00 = baseA[i][0] + (((2 * ks + 0) << 2) ^ swA[i][0]);
                int a01 = baseA[i][1] + (((2 * ks + 0) << 2) ^ swA[i][1]);
                int a10 = baseA[i][0] + (((2 * ks + 1) << 2) ^ swA[i][0]);
                int a11 = baseA[i][1] + (((2 * ks + 1) << 2) ^ swA[i][1]);
                ahf[i][0] = St[a00]; ahf[i][1] = St[a01];
                ahf[i][2] = St[a10]; ahf[i][3] = St[a11];
                alf[i][0] = Alp[a00]; alf[i][1] = Alp[a01];
                alf[i][2] = Alp[a10]; alf[i][3] = Alp[a11];
            }
#pragma unroll
            for (int j = 0; j < 8; j++) {
                int b0 = baseB[j] + (((2 * ks + 0) << 2) ^ swB[j]);
                int b1 = baseB[j] + (((2 * ks + 1) << 2) ^ swB[j]);
                unsigned bh0 = Bhp[b0], bh1 = Bhp[b1];
                unsigned bl0 = Blp[b0], bl1 = Blp[b1];
                mma_bf16(acc[0][j], ahf[0], bh0, bh1);
                mma_bf16(acc[1][j], ahf[1], bh0, bh1);
                mma_bf16(acc[0][j], ahf[0], bl0, bl1);
                mma_bf16(acc[1][j], ahf[1], bl0, bl1);
                mma_bf16(acc[0][j], alf[0], bh0, bh1);
                mma_bf16(acc[1][j], alf[1], bh0, bh1);
            }
        }
        if (++slot == 3) slot = 0;
    }

    // epilogue
#pragma unroll
    for (int i = 0; i < 2; i++) {
        int orow = bm + wm * 32 + i * 16 + fg;
#pragma unroll
        for (int j = 0; j < 8; j++) {
            int col = bn + wn * 64 + j * 8 + ft * 2;
            float b0 = bias[col], b1 = bias[col + 1];
            float v0 = acc[i][j][0] + b0;
            float v1 = acc[i][j][1] + b1;
            float v2 = acc[i][j][2] + b0;
            float v3 = acc[i][j][3] + b1;
            if (act == 1) {
                v0 = v0 / (1.f + __expf(-v0));
                v1 = v1 / (1.f + __expf(-v1));
                v2 = v2 / (1.f + __expf(-v2));
                v3 = v3 / (1.f + __expf(-v3));
            }
            *(float2*)&C[(size_t)orow * N + col] = make_float2(v0, v1);
            *(float2*)&C[(size_t)(orow + 8) * N + col] = make_float2(v2, v3);
        }
    }
}

// ===========================================================================
// Legacy bf16x3 GEMM (R5-exact) for the small ctrl GEMM (N=80, unpadded)
// ===========================================================================
#define TBM 128
#define TBK 16
#define XSTR 12
#define PLANE (TBM * XSTR)

__global__ __launch_bounds__(256) void gemm_bf16x3(
    const float* __restrict__ A, const float* __restrict__ B,
    const float* __restrict__ bias, float* __restrict__ C,
    int M, int N, int K, int act)
{
    __shared__ __align__(16) unsigned As[2][2 * PLANE];
    __shared__ __align__(16) unsigned Bs[2][2 * PLANE];

    int tid  = threadIdx.x;
    int lane = tid & 31;
    int warp = tid >> 5;
    int wm = warp >> 1, wn = warp & 1;
    int bm = blockIdx.y * TBM;
    int bn = blockIdx.x * 128;

    int arow = tid >> 1, ah = tid & 1;
    const float* Aptr = A + (size_t)(bm + arow) * K + ah * 8;
    int xa = (arow & 3) ^ ((arow >> 3) & 3);
    int ast_base = arow * XSTR + 4 * ah;
    int bnn = tid & 127, bh2 = tid >> 7;
    int gcol = bn + bnn;
    int xb = (bnn & 3) ^ ((bnn >> 3) & 3);
    int bst_base = bnn * XSTR + 4 * bh2;

    int fg = lane >> 2, ft = lane & 3;
    int idxA[2][2];
#pragma unroll
    for (int i = 0; i < 2; i++)
#pragma unroll
        for (int d = 0; d < 2; d++) {
            int row = wm * 32 + i * 16 + d * 8 + fg;
            idxA[i][d] = row * XSTR + (ft ^ (row & 3) ^ ((row >> 3) & 3));
        }
    int idxB[8];
#pragma unroll
    for (int j = 0; j < 8; j++) {
        int n = wn * 64 + j * 8 + fg;
        idxB[j] = n * XSTR + (ft ^ (n & 3) ^ ((n >> 3) & 3));
    }

    float acc[2][8][4];
#pragma unroll
    for (int i = 0; i < 2; i++)
#pragma unroll
        for (int j = 0; j < 8; j++)
#pragma unroll
            for (int l = 0; l < 4; l++) acc[i][j][l] = 0.f;

    {
        float4 f0 = *(const float4*)Aptr;
        float4 f1 = *(const float4*)(Aptr + 4);
        unsigned hi, lo;
        split2(f0.x, f0.y, hi, lo);
        As[0][ast_base + (0 ^ xa)] = hi; As[0][PLANE + ast_base + (0 ^ xa)] = lo;
        split2(f0.z, f0.w, hi, lo);
        As[0][ast_base + (1 ^ xa)] = hi; As[0][PLANE + ast_base + (1 ^ xa)] = lo;
        split2(f1.x, f1.y, hi, lo);
        As[0][ast_base + (2 ^ xa)] = hi; As[0][PLANE + ast_base + (2 ^ xa)] = lo;
        split2(f1.z, f1.w, hi, lo);
        As[0][ast_base + (3 ^ xa)] = hi; As[0][PLANE + ast_base + (3 ^ xa)] = lo;
#pragma unroll
        for (int i = 0; i < 4; i++) {
            int k = 8 * bh2 + 2 * i;
            float b0 = (gcol < N) ? B[(size_t)k * N + gcol] : 0.f;
            float b1 = (gcol < N) ? B[(size_t)(k + 1) * N + gcol] : 0.f;
            split2(b0, b1, hi, lo);
            Bs[0][bst_base + (i ^ xb)] = hi;
            Bs[0][PLANE + bst_base + (i ^ xb)] = lo;
        }
    }
    __syncthreads();

    int iters = K / TBK;
    for (int it = 1; it <= iters; it++) {
        bool has = (it < iters);
        float4 f0, f1;
        float bg[8];
        if (has) {
            int k0 = it * TBK;
            f0 = *(const float4*)(Aptr + k0);
            f1 = *(const float4*)(Aptr + k0 + 4);
#pragma unroll
            for (int i = 0; i < 4; i++) {
                int k = k0 + 8 * bh2 + 2 * i;
                bg[2 * i]     = (gcol < N) ? B[(size_t)k * N + gcol] : 0.f;
                bg[2 * i + 1] = (gcol < N) ? B[(size_t)(k + 1) * N + gcol] : 0.f;
            }
        }
        {
            const unsigned* Ab = As[(it - 1) & 1];
            const unsigned* Bb = Bs[(it - 1) & 1];
            unsigned ahf[2][4], alf[2][4];
#pragma unroll
            for (int i = 0; i < 2; i++) {
                ahf[i][0] = Ab[idxA[i][0]];
                ahf[i][1] = Ab[idxA[i][1]];
                ahf[i][2] = Ab[idxA[i][0] + 4];
                ahf[i][3] = Ab[idxA[i][1] + 4];
                alf[i][0] = Ab[PLANE + idxA[i][0]];
                alf[i][1] = Ab[PLANE + idxA[i][1]];
                alf[i][2] = Ab[PLANE + idxA[i][0] + 4];
                alf[i][3] = Ab[PLANE + idxA[i][1] + 4];
            }
#pragma unroll
            for (int j = 0; j < 8; j++) {
                unsigned bh0 = Bb[idxB[j]];
                unsigned bh1 = Bb[idxB[j] + 4];
                unsigned bl0 = Bb[PLANE + idxB[j]];
                unsigned bl1 = Bb[PLANE + idxB[j] + 4];
                mma_bf16(acc[0][j], ahf[0], bh0, bh1);
                mma_bf16(acc[1][j], ahf[1], bh0, bh1);
                mma_bf16(acc[0][j], ahf[0], bl0, bl1);
                mma_bf16(acc[1][j], ahf[1], bl0, bl1);
                mma_bf16(acc[0][j], alf[0], bh0, bh1);
                mma_bf16(acc[1][j], alf[1], bh0, bh1);
            }
        }
        if (has) {
            int buf = it & 1;
            unsigned hi, lo;
            split2(f0.x, f0.y, hi, lo);
            As[buf][ast_base + (0 ^ xa)] = hi; As[buf][PLANE + ast_base + (0 ^ xa)] = lo;
            split2(f0.z, f0.w, hi, lo);
            As[buf][ast_base + (1 ^ xa)] = hi; As[buf][PLANE + ast_base + (1 ^ xa)] = lo;
            split2(f1.x, f1.y, hi, lo);
            As[buf][ast_base + (2 ^ xa)] = hi; As[buf][PLANE + ast_base + (2 ^ xa)] = lo;
            split2(f1.z, f1.w, hi, lo);
            As[buf][ast_base + (3 ^ xa)] = hi; As[buf][PLANE + ast_base + (3 ^ xa)] = lo;
#pragma unroll
            for (int i = 0; i < 4; i++) {
                split2(bg[2 * i], bg[2 * i + 1], hi, lo);
                Bs[buf][bst_base + (i ^ xb)] = hi;
                Bs[buf][PLANE + bst_base + (i ^ xb)] = lo;
            }
        }
        __syncthreads();
    }

#pragma unroll
    for (int i = 0; i < 2; i++) {
        int row = bm + wm * 32 + i * 16 + fg;
#pragma unroll
        for (int j = 0; j < 8; j++) {
            int col = bn + wn * 64 + j * 8 + ft * 2;
            if (col < N) {
                float b0 = bias[col], b1 = bias[col + 1];
                float v0 = acc[i][j][0] + b0;
                float v1 = acc[i][j][1] + b1;
                float v2 = acc[i][j][2] + b0;
                float v3 = acc[i][j][3] + b1;
                if (act == 1) {
                    v0 = v0 / (1.f + __expf(-v0));
                    v1 = v1 / (1.f + __expf(-v1));
                    v2 = v2 / (1.f + __expf(-v2));
                    v3 = v3 / (1.f + __expf(-v3));
                }
                *(float2*)&C[(size_t)row * N + col] = make_float2(v0, v1);
                *(float2*)&C[(size_t)(row + 8) * N + col] = make_float2(v2, v3);
            }
        }
    }
}

// ===========================================================================
// Sequential scan (R5-exact: block-wide cp.async, SDEPTH=4)
// ===========================================================================
#define SDEPTH 4
#define SBUF 224

__global__ __launch_bounds__(128) void scan_kernel(
    const float* __restrict__ base,
    const float* __restrict__ ctrl,
    const float* __restrict__ memory0,
    float* __restrict__ ys,
    float* __restrict__ mfinal)
{
    __shared__ __align__(16) float sbuf[SDEPTH][SBUF];

    int bh   = blockIdx.x >> 1;
    int half = blockIdx.x & 1;
    int b = bh >> 4, h = bh & 15;
    int tid = threadIdx.x;
    int r = (tid >> 2) + half * 32;
    int g = tid & 3;

    float m[16];
    {
        const float* M0 = memory0 + (((size_t)bh * HDIM + r) * HDIM + g * 16);
#pragma unroll
        for (int jj = 0; jj < 16; jj++) m[jj] = M0[jj];
    }

    const float* bsrc = base + ((size_t)b * SS * HH + h) * 192;
    const float* csrc = ctrl + (size_t)b * SS * 80 + h * 5;
    float* yptr = ys + (size_t)b * SS * DD + h * HDIM + r;

    unsigned sb_addr[SDEPTH];
#pragma unroll
    for (int d = 0; d < SDEPTH; d++)
        sb_addr[d] = (unsigned)__cvta_generic_to_shared(&sbuf[d][0]);

#pragma unroll
    for (int p = 0; p < SDEPTH - 1; p++) {
        unsigned sa = sb_addr[p & (SDEPTH - 1)];
        const float* bp = bsrc + (size_t)p * 3072;
        if (tid < 64) {
            cpa4(sa + tid * 4,         bp + tid);
            cpa4(sa + (64 + tid) * 4,  bp + 64 + tid);
            cpa4(sa + (128 + tid) * 4, bp + 128 + tid);
        } else if (tid < 69) {
            cpa4(sa + (192 + tid - 64) * 4, csrc + (size_t)p * 80 + (tid - 64));
        }
        cpcommit();
    }

    for (int s = 0; s < SS; s++) {
        cpwait<2>();
        __syncthreads();

        int pf = s + SDEPTH - 1;
        if (pf < SS) {
            unsigned sa = sb_addr[pf & (SDEPTH - 1)];
            const float* bp = bsrc + (size_t)pf * 3072;
            if (tid < 64) {
                cpa4(sa + tid * 4,         bp + tid);
                cpa4(sa + (64 + tid) * 4,  bp + 64 + tid);
                cpa4(sa + (128 + tid) * 4, bp + 128 + tid);
            } else if (tid < 69) {
                cpa4(sa + (192 + tid - 64) * 4, csrc + (size_t)pf * 80 + (tid - 64));
            }
        }
        cpcommit();

        const float* sb = sbuf[s & (SDEPTH - 1)];
        float c0 = sb[192], c1 = sb[193], c2 = sb[194];
        float eta   = 1.f / (1.f + __expf(-sb[195]));
        float alpha = 1.f / (1.f + __expf(-sb[196]));

        float kr[16], qr[16];
#pragma unroll
        for (int w = 0; w < 4; w++) {
            *(float4*)&kr[w * 4] = *(const float4*)&sb[g * 16 + w * 4];
            *(float4*)&qr[w * 4] = *(const float4*)&sb[128 + g * 16 + w * 4];
        }
        float dq0 = 0.f, dq1 = 0.f, dk0 = 0.f, dk1 = 0.f;
#pragma unroll
        for (int jj = 0; jj < 16; jj += 2) {
            dq0 += m[jj] * qr[jj];
            dq1 += m[jj + 1] * qr[jj + 1];
            dk0 += m[jj] * kr[jj];
            dk1 += m[jj + 1] * kr[jj + 1];
        }
        float dq = dq0 + dq1, dk = dk0 + dk1;
        dq += __shfl_xor_sync(0xffffffffu, dq, 1);
        dq += __shfl_xor_sync(0xffffffffu, dq, 2);
        dk += __shfl_xor_sync(0xffffffffu, dk, 1);
        dk += __shfl_xor_sync(0xffffffffu, dk, 2);

        float err = c0 * dk - c1 * sb[64 + r];
        if (g == 0) yptr[(size_t)s * DD] = c2 * dq;

        float ekc = eta * err * c0;
#pragma unroll
        for (int jj = 0; jj < 16; jj++)
            m[jj] = alpha * m[jj] + ekc * kr[jj];
    }

    float* MF = mfinal + (((size_t)bh * HDIM + r) * HDIM + g * 16);
#pragma unroll
    for (int jj = 0; jj < 16; jj++) MF[jj] = m[jj];
}

// ===========================================================================
extern "C" void kernel_launch(void* const* d_in, const int* in_sizes, int n_in,
                              void* d_out, int out_size)
{
    (void)in_sizes; (void)n_in;
    const float* x       = (const float*)d_in[0];
    const float* memory0 = (const float*)d_in[1];
    const float* W_in    = (const float*)d_in[2];
    const float* b_in    = (const float*)d_in[3];
    const float* Wc1     = (const float*)d_in[4];
    const float* bc1     = (const float*)d_in[5];
    const float* Wc2     = (const float*)d_in[6];
    const float* bc2     = (const float*)d_in[7];
    const float* W_out   = (const float*)d_in[8];
    const float* b_out   = (const float*)d_in[9];

    float* out = (float*)d_out;

    float *base, *hidden, *ctrl, *ys, *mf_scratch;
    cudaGetSymbolAddress((void**)&base,       g_base);
    cudaGetSymbolAddress((void**)&hidden,     g_hidden);
    cudaGetSymbolAddress((void**)&ctrl,       g_ctrl);
    cudaGetSymbolAddress((void**)&ys,         g_ys);
    cudaGetSymbolAddress((void**)&mf_scratch, g_mf);

    __nv_bfloat16 *xh, *xl, *ysh, *ysl, *w1h, *w1l, *wc1h, *wc1l, *woh, *wol;
    cudaGetSymbolAddress((void**)&xh,  g_xh);   cudaGetSymbolAddress((void**)&xl,  g_xl);
    cudaGetSymbolAddress((void**)&ysh, g_ysh);  cudaGetSymbolAddress((void**)&ysl, g_ysl);
    cudaGetSymbolAddress((void**)&w1h, g_w1h);  cudaGetSymbolAddress((void**)&w1l, g_w1l);
    cudaGetSymbolAddress((void**)&wc1h, g_wc1h); cudaGetSymbolAddress((void**)&wc1l, g_wc1l);
    cudaGetSymbolAddress((void**)&woh, g_woh);  cudaGetSymbolAddress((void**)&wol, g_wol);

    const size_t OUT_ELEMS = (size_t)MR * DD;
    const size_t MF_ELEMS  = (size_t)BB * HH * HDIM * HDIM;
    float* mfinal = ((size_t)out_size >= OUT_ELEMS + MF_ELEMS)
                        ? (out + OUT_ELEMS) : mf_scratch;

    cudaFuncSetAttribute(gemm_fast, cudaFuncAttributeMaxDynamicSharedMemorySize,
                         V2SMEM);

    // pre-split inputs / weights
    split_rows<<<MR * DD / 1024, 256>>>(x, xh, xl);
    splitT<<<dim3(3 * DD / 32, DD / 32), dim3(32, 8)>>>(W_in, w1h, w1l, DD, 3 * DD);
    splitT<<<dim3(DD / 32, DD / 32), dim3(32, 8)>>>(Wc1, wc1h, wc1l, DD, DD);
    splitT<<<dim3(DD / 32, DD / 32), dim3(32, 8)>>>(W_out, woh, wol, DD, DD);

    // base = x @ W_in + b_in
    gemm_fast<<<dim3(3 * DD / 128, MR / 128), 256, V2SMEM>>>(
        xh, xl, w1h, w1l, b_in, base, MR, 3 * DD, DD, 0);
    // hidden = silu(x @ Wc1 + bc1)
    gemm_fast<<<dim3(DD / 128, MR / 128), 256, V2SMEM>>>(
        xh, xl, wc1h, wc1l, bc1, hidden, MR, DD, DD, 1);
    // ctrl = hidden @ Wc2 + bc2   (N=80, unpadded, R5 path)
    gemm_bf16x3<<<dim3(1, MR / TBM), 256>>>(
        hidden, Wc2, bc2, ctrl, MR, 5 * HH, DD, 0);
    // sequential scan (R5 path)
    scan_kernel<<<BB * HH * 2, 128>>>(base, ctrl, memory0, ys, mfinal);
    // out = ys @ W_out + b_out
    split_rows<<<MR * DD / 1024, 256>>>(ys, ysh, ysl);
    gemm_fast<<<dim3(DD / 128, MR / 128), 256, V2SMEM>>>(
        ysh, ysl, woh, wol, b_out, out, MR, DD, DD, 0);
}

// round 9
// speedup vs baseline: 1.2729x; 1.0700x over previous
#include <cuda_runtime.h>
#include <cuda_bf16.h>
#include <math.h>
#include <stdint.h>

#define BB 4
#define SS 2048
#define DD 1024
#define HH 16
#define HDIM 64
#define MR (BB * SS)   // 8192

// ---- scratch (device globals: allocation-free per harness rules) ----
__device__ float g_base[(size_t)MR * 3 * DD];      // [8192,3072]
__device__ float g_hidden[(size_t)MR * DD];        // [8192,1024]
__device__ float g_ctrl[(size_t)MR * 80 + 16];     // [8192,80] (+pad for 16B tail reads)
__device__ float g_ys[(size_t)MR * DD];            // [8192,1024]
__device__ float g_mf[(size_t)BB * HH * HDIM * HDIM];

// ===========================================================================
// helpers
// ===========================================================================
__device__ __forceinline__ void split2(float a0, float a1,
                                       unsigned& hi, unsigned& lo) {
    asm("cvt.rn.bf16x2.f32 %0, %1, %2;" : "=r"(hi) : "f"(a1), "f"(a0));
    float h0 = __uint_as_float(hi << 16);
    float h1 = __uint_as_float(hi & 0xffff0000u);
    float r0 = a0 - h0, r1 = a1 - h1;
    asm("cvt.rn.bf16x2.f32 %0, %1, %2;" : "=r"(lo) : "f"(r1), "f"(r0));
}

__device__ __forceinline__ void mma_bf16(float* c, const unsigned* a,
                                         unsigned b0, unsigned b1) {
    asm volatile(
        "mma.sync.aligned.m16n8k16.row.col.f32.bf16.bf16.f32 "
        "{%0,%1,%2,%3}, {%4,%5,%6,%7}, {%8,%9}, {%0,%1,%2,%3};"
        : "+f"(c[0]), "+f"(c[1]), "+f"(c[2]), "+f"(c[3])
        : "r"(a[0]), "r"(a[1]), "r"(a[2]), "r"(a[3]), "r"(b0), "r"(b1));
}

__device__ __forceinline__ void cpa16(uint32_t s, const void* g) {
    asm volatile("cp.async.ca.shared.global [%0], [%1], 16;"
                 :: "r"(s), "l"(g) : "memory");
}
__device__ __forceinline__ void cpa4(uint32_t s, const void* g) {
    asm volatile("cp.async.ca.shared.global [%0], [%1], 4;"
                 :: "r"(s), "l"(g) : "memory");
}
__device__ __forceinline__ void cpcommit() {
    asm volatile("cp.async.commit_group;" ::: "memory");
}
template <int N>
__device__ __forceinline__ void cpwait() {
    asm volatile("cp.async.wait_group %0;" :: "n"(N) : "memory");
}

// ===========================================================================
// Legacy bf16x3 GEMM (R5-exact): C = act(A @ B + bias), fp32 in/out.
// 128x128x16 tile, 256 threads, 8 warps (warp tile 32x64), mma.m16n8k16.
// ===========================================================================
#define TBM 128
#define TBK 16
#define XSTR 12
#define PLANE (TBM * XSTR)

__global__ __launch_bounds__(256) void gemm_bf16x3(
    const float* __restrict__ A, const float* __restrict__ B,
    const float* __restrict__ bias, float* __restrict__ C,
    int M, int N, int K, int act)
{
    __shared__ __align__(16) unsigned As[2][2 * PLANE];
    __shared__ __align__(16) unsigned Bs[2][2 * PLANE];

    int tid  = threadIdx.x;
    int lane = tid & 31;
    int warp = tid >> 5;
    int wm = warp >> 1, wn = warp & 1;
    int bm = blockIdx.y * TBM;
    int bn = blockIdx.x * 128;

    int arow = tid >> 1, ah = tid & 1;
    const float* Aptr = A + (size_t)(bm + arow) * K + ah * 8;
    int xa = (arow & 3) ^ ((arow >> 3) & 3);
    int ast_base = arow * XSTR + 4 * ah;
    int bnn = tid & 127, bh2 = tid >> 7;
    int gcol = bn + bnn;
    int xb = (bnn & 3) ^ ((bnn >> 3) & 3);
    int bst_base = bnn * XSTR + 4 * bh2;

    int fg = lane >> 2, ft = lane & 3;
    int idxA[2][2];
#pragma unroll
    for (int i = 0; i < 2; i++)
#pragma unroll
        for (int d = 0; d < 2; d++) {
            int row = wm * 32 + i * 16 + d * 8 + fg;
            idxA[i][d] = row * XSTR + (ft ^ (row & 3) ^ ((row >> 3) & 3));
        }
    int idxB[8];
#pragma unroll
    for (int j = 0; j < 8; j++) {
        int n = wn * 64 + j * 8 + fg;
        idxB[j] = n * XSTR + (ft ^ (n & 3) ^ ((n >> 3) & 3));
    }

    float acc[2][8][4];
#pragma unroll
    for (int i = 0; i < 2; i++)
#pragma unroll
        for (int j = 0; j < 8; j++)
#pragma unroll
            for (int l = 0; l < 4; l++) acc[i][j][l] = 0.f;

    {
        float4 f0 = *(const float4*)Aptr;
        float4 f1 = *(const float4*)(Aptr + 4);
        unsigned hi, lo;
        split2(f0.x, f0.y, hi, lo);
        As[0][ast_base + (0 ^ xa)] = hi; As[0][PLANE + ast_base + (0 ^ xa)] = lo;
        split2(f0.z, f0.w, hi, lo);
        As[0][ast_base + (1 ^ xa)] = hi; As[0][PLANE + ast_base + (1 ^ xa)] = lo;
        split2(f1.x, f1.y, hi, lo);
        As[0][ast_base + (2 ^ xa)] = hi; As[0][PLANE + ast_base + (2 ^ xa)] = lo;
        split2(f1.z, f1.w, hi, lo);
        As[0][ast_base + (3 ^ xa)] = hi; As[0][PLANE + ast_base + (3 ^ xa)] = lo;
#pragma unroll
        for (int i = 0; i < 4; i++) {
            int k = 8 * bh2 + 2 * i;
            float b0 = (gcol < N) ? B[(size_t)k * N + gcol] : 0.f;
            float b1 = (gcol < N) ? B[(size_t)(k + 1) * N + gcol] : 0.f;
            split2(b0, b1, hi, lo);
            Bs[0][bst_base + (i ^ xb)] = hi;
            Bs[0][PLANE + bst_base + (i ^ xb)] = lo;
        }
    }
    __syncthreads();

    int iters = K / TBK;
    for (int it = 1; it <= iters; it++) {
        bool has = (it < iters);
        float4 f0, f1;
        float bg[8];
        if (has) {
            int k0 = it * TBK;
            f0 = *(const float4*)(Aptr + k0);
            f1 = *(const float4*)(Aptr + k0 + 4);
#pragma unroll
            for (int i = 0; i < 4; i++) {
                int k = k0 + 8 * bh2 + 2 * i;
                bg[2 * i]     = (gcol < N) ? B[(size_t)k * N + gcol] : 0.f;
                bg[2 * i + 1] = (gcol < N) ? B[(size_t)(k + 1) * N + gcol] : 0.f;
            }
        }
        {
            const unsigned* Ab = As[(it - 1) & 1];
            const unsigned* Bb = Bs[(it - 1) & 1];
            unsigned ahf[2][4], alf[2][4];
#pragma unroll
            for (int i = 0; i < 2; i++) {
                ahf[i][0] = Ab[idxA[i][0]];
                ahf[i][1] = Ab[idxA[i][1]];
                ahf[i][2] = Ab[idxA[i][0] + 4];
                ahf[i][3] = Ab[idxA[i][1] + 4];
                alf[i][0] = Ab[PLANE + idxA[i][0]];
                alf[i][1] = Ab[PLANE + idxA[i][1]];
                alf[i][2] = Ab[PLANE + idxA[i][0] + 4];
                alf[i][3] = Ab[PLANE + idxA[i][1] + 4];
            }
#pragma unroll
            for (int j = 0; j < 8; j++) {
                unsigned bh0 = Bb[idxB[j]];
                unsigned bh1 = Bb[idxB[j] + 4];
                unsigned bl0 = Bb[PLANE + idxB[j]];
                unsigned bl1 = Bb[PLANE + idxB[j] + 4];
                mma_bf16(acc[0][j], ahf[0], bh0, bh1);
                mma_bf16(acc[1][j], ahf[1], bh0, bh1);
                mma_bf16(acc[0][j], ahf[0], bl0, bl1);
                mma_bf16(acc[1][j], ahf[1], bl0, bl1);
                mma_bf16(acc[0][j], alf[0], bh0, bh1);
                mma_bf16(acc[1][j], alf[1], bh0, bh1);
            }
        }
        if (has) {
            int buf = it & 1;
            unsigned hi, lo;
            split2(f0.x, f0.y, hi, lo);
            As[buf][ast_base + (0 ^ xa)] = hi; As[buf][PLANE + ast_base + (0 ^ xa)] = lo;
            split2(f0.z, f0.w, hi, lo);
            As[buf][ast_base + (1 ^ xa)] = hi; As[buf][PLANE + ast_base + (1 ^ xa)] = lo;
            split2(f1.x, f1.y, hi, lo);
            As[buf][ast_base + (2 ^ xa)] = hi; As[buf][PLANE + ast_base + (2 ^ xa)] = lo;
            split2(f1.z, f1.w, hi, lo);
            As[buf][ast_base + (3 ^ xa)] = hi; As[buf][PLANE + ast_base + (3 ^ xa)] = lo;
#pragma unroll
            for (int i = 0; i < 4; i++) {
                split2(bg[2 * i], bg[2 * i + 1], hi, lo);
                Bs[buf][bst_base + (i ^ xb)] = hi;
                Bs[buf][PLANE + bst_base + (i ^ xb)] = lo;
            }
        }
        __syncthreads();
    }

#pragma unroll
    for (int i = 0; i < 2; i++) {
        int row = bm + wm * 32 + i * 16 + fg;
#pragma unroll
        for (int j = 0; j < 8; j++) {
            int col = bn + wn * 64 + j * 8 + ft * 2;
            if (col < N) {
                float b0 = bias[col], b1 = bias[col + 1];
                float v0 = acc[i][j][0] + b0;
                float v1 = acc[i][j][1] + b1;
                float v2 = acc[i][j][2] + b0;
                float v3 = acc[i][j][3] + b1;
                if (act == 1) {
                    v0 = v0 / (1.f + __expf(-v0));
                    v1 = v1 / (1.f + __expf(-v1));
                    v2 = v2 / (1.f + __expf(-v2));
                    v3 = v3 / (1.f + __expf(-v3));
                }
                *(float2*)&C[(size_t)row * N + col] = make_float2(v0, v1);
                *(float2*)&C[(size_t)(row + 8) * N + col] = make_float2(v2, v3);
            }
        }
    }
}

// ===========================================================================
// Sequential scan v3: SDEPTH=8 ring, 16B cp.async for k/v/q (threads 0-47),
// 4B for ctrl (threads 48-52). wait_group<7> waits ONLY group s (7-step
// prefetch cover ~>1400cyc, exceeds DRAM latency). One __syncthreads/step.
// Per-step math identical to R5.
// ===========================================================================
#define SDEPTH 8
#define SBUF 224   // floats/stage: k[0:64) v[64:128) q[128:192) ctrl[192:197)

__global__ __launch_bounds__(128) void scan_kernel(
    const float* __restrict__ base,    // [B,S,H,3,HD]
    const float* __restrict__ ctrl,    // [B,S,H,5]
    const float* __restrict__ memory0, // [B,H,HD,HD]
    float* __restrict__ ys,            // [B,S,D]
    float* __restrict__ mfinal)        // [B,H,HD,HD]
{
    __shared__ __align__(16) float sbuf[SDEPTH][SBUF];

    int bh   = blockIdx.x >> 1;
    int half = blockIdx.x & 1;
    int b = bh >> 4, h = bh & 15;
    int tid = threadIdx.x;
    int r = (tid >> 2) + half * 32;
    int g = tid & 3;

    float m[16];
    {
        const float* M0 = memory0 + (((size_t)bh * HDIM + r) * HDIM + g * 16);
#pragma unroll
        for (int jj = 0; jj < 16; jj++) m[jj] = M0[jj];
    }

    const float* bsrc = base + ((size_t)b * SS * HH + h) * 192;  // 768B-aligned
    const float* csrc = ctrl + (size_t)b * SS * 80 + h * 5;
    float* yptr = ys + (size_t)b * SS * DD + h * HDIM + r;

    unsigned sb_addr[SDEPTH];
#pragma unroll
    for (int d = 0; d < SDEPTH; d++)
        sb_addr[d] = (unsigned)__cvta_generic_to_shared(&sbuf[d][0]);

#define SCAN_ISSUE(st) do {                                              \
        unsigned sa_ = sb_addr[(st) & (SDEPTH - 1)];                     \
        if (tid < 48)                                                    \
            cpa16(sa_ + tid * 16, bsrc + (size_t)(st) * 3072 + tid * 4); \
        else if (tid < 53)                                               \
            cpa4(sa_ + 768 + (tid - 48) * 4,                             \
                 csrc + (size_t)(st) * 80 + (tid - 48));                 \
        cpcommit();                                                      \
    } while (0)

    // prologue: stages 0..6 in flight (7 groups/thread)
#pragma unroll
    for (int p = 0; p < SDEPTH - 1; p++) SCAN_ISSUE(p);

    for (int s = 0; s < SS; s++) {
        // issue stage s+7 first (keeps 8 groups outstanding), then wait for s
        if (s + SDEPTH - 1 < SS) SCAN_ISSUE(s + SDEPTH - 1);
        else cpcommit();
        cpwait<SDEPTH - 1>();   // waits only group s
        __syncthreads();

        const float* sb = sbuf[s & (SDEPTH - 1)];
        float c0 = sb[192], c1 = sb[193], c2 = sb[194];
        float eta   = 1.f / (1.f + __expf(-sb[195]));
        float alpha = 1.f / (1.f + __expf(-sb[196]));

        float kr[16], qr[16];
#pragma unroll
        for (int w = 0; w < 4; w++) {
            *(float4*)&kr[w * 4] = *(const float4*)&sb[g * 16 + w * 4];
            *(float4*)&qr[w * 4] = *(const float4*)&sb[128 + g * 16 + w * 4];
        }
        float dq0 = 0.f, dq1 = 0.f, dk0 = 0.f, dk1 = 0.f;
#pragma unroll
        for (int jj = 0; jj < 16; jj += 2) {
            dq0 += m[jj] * qr[jj];
            dq1 += m[jj + 1] * qr[jj + 1];
            dk0 += m[jj] * kr[jj];
            dk1 += m[jj + 1] * kr[jj + 1];
        }
        float dq = dq0 + dq1, dk = dk0 + dk1;
        dq += __shfl_xor_sync(0xffffffffu, dq, 1);
        dq += __shfl_xor_sync(0xffffffffu, dq, 2);
        dk += __shfl_xor_sync(0xffffffffu, dk, 1);
        dk += __shfl_xor_sync(0xffffffffu, dk, 2);

        float err = c0 * dk - c1 * sb[64 + r];
        if (g == 0) yptr[(size_t)s * DD] = c2 * dq;

        float ekc = eta * err * c0;
#pragma unroll
        for (int jj = 0; jj < 16; jj++)
            m[jj] = alpha * m[jj] + ekc * kr[jj];

        __syncthreads();   // all reads of stage s done before its slot is reused
    }

    float* MF = mfinal + (((size_t)bh * HDIM + r) * HDIM + g * 16);
#pragma unroll
    for (int jj = 0; jj < 16; jj++) MF[jj] = m[jj];
}

// ===========================================================================
extern "C" void kernel_launch(void* const* d_in, const int* in_sizes, int n_in,
                              void* d_out, int out_size)
{
    (void)in_sizes; (void)n_in;
    const float* x       = (const float*)d_in[0];
    const float* memory0 = (const float*)d_in[1];
    const float* W_in    = (const float*)d_in[2];
    const float* b_in    = (const float*)d_in[3];
    const float* Wc1     = (const float*)d_in[4];
    const float* bc1     = (const float*)d_in[5];
    const float* Wc2     = (const float*)d_in[6];
    const float* bc2     = (const float*)d_in[7];
    const float* W_out   = (const float*)d_in[8];
    const float* b_out   = (const float*)d_in[9];

    float* out = (float*)d_out;

    float *base, *hidden, *ctrl, *ys, *mf_scratch;
    cudaGetSymbolAddress((void**)&base,       g_base);
    cudaGetSymbolAddress((void**)&hidden,     g_hidden);
    cudaGetSymbolAddress((void**)&ctrl,       g_ctrl);
    cudaGetSymbolAddress((void**)&ys,         g_ys);
    cudaGetSymbolAddress((void**)&mf_scratch, g_mf);

    const size_t OUT_ELEMS = (size_t)MR * DD;
    const size_t MF_ELEMS  = (size_t)BB * HH * HDIM * HDIM;
    float* mfinal = ((size_t)out_size >= OUT_ELEMS + MF_ELEMS)
                        ? (out + OUT_ELEMS) : mf_scratch;

    // base = x @ W_in + b_in                  [8192,3072]
    gemm_bf16x3<<<dim3(3 * DD / 128, MR / TBM), 256>>>(
        x, W_in, b_in, base, MR, 3 * DD, DD, 0);
    // hidden = silu(x @ Wc1 + bc1)            [8192,1024]
    gemm_bf16x3<<<dim3(DD / 128, MR / TBM), 256>>>(
        x, Wc1, bc1, hidden, MR, DD, DD, 1);
    // ctrl = hidden @ Wc2 + bc2               [8192,80]
    gemm_bf16x3<<<dim3(1, MR / TBM), 256>>>(
        hidden, Wc2, bc2, ctrl, MR, 5 * HH, DD, 0);
    // sequential scan
    scan_kernel<<<BB * HH * 2, 128>>>(base, ctrl, memory0, ys, mfinal);
    // out = ys @ W_out + b_out                [8192,1024]
    gemm_bf16x3<<<dim3(DD / 128, MR / TBM), 256>>>(
        ys, W_out, b_out, out, MR, DD, DD, 0);
}

// round 11
// speedup vs baseline: 1.2805x; 1.0060x over previous
#include <cuda_runtime.h>
#include <cuda_bf16.h>
#include <math.h>
#include <stdint.h>

#define BB 4
#define SS 2048
#define DD 1024
#define HH 16
#define HDIM 64
#define MR (BB * SS)   // 8192

// ---- scratch (device globals: allocation-free per harness rules) ----
__device__ float g_base[(size_t)MR * 3 * DD];      // [8192,3072]
__device__ float g_hidden[(size_t)MR * DD];        // [8192,1024]
__device__ float g_ctrl[(size_t)MR * 80 + 16];     // [8192,80] (+pad)
__device__ float g_ys[(size_t)MR * DD];            // [8192,1024]
__device__ float g_mf[(size_t)BB * HH * HDIM * HDIM];

// ===========================================================================
// helpers
// ===========================================================================
__device__ __forceinline__ void split2(float a0, float a1,
                                       unsigned& hi, unsigned& lo) {
    asm("cvt.rn.bf16x2.f32 %0, %1, %2;" : "=r"(hi) : "f"(a1), "f"(a0));
    float h0 = __uint_as_float(hi << 16);
    float h1 = __uint_as_float(hi & 0xffff0000u);
    float r0 = a0 - h0, r1 = a1 - h1;
    asm("cvt.rn.bf16x2.f32 %0, %1, %2;" : "=r"(lo) : "f"(r1), "f"(r0));
}

__device__ __forceinline__ void mma_bf16(float* c, const unsigned* a,
                                         unsigned b0, unsigned b1) {
    asm volatile(
        "mma.sync.aligned.m16n8k16.row.col.f32.bf16.bf16.f32 "
        "{%0,%1,%2,%3}, {%4,%5,%6,%7}, {%8,%9}, {%0,%1,%2,%3};"
        : "+f"(c[0]), "+f"(c[1]), "+f"(c[2]), "+f"(c[3])
        : "r"(a[0]), "r"(a[1]), "r"(a[2]), "r"(a[3]), "r"(b0), "r"(b1));
}

__device__ __forceinline__ void cpa16(uint32_t s, const void* g) {
    asm volatile("cp.async.ca.shared.global [%0], [%1], 16;"
                 :: "r"(s), "l"(g) : "memory");
}
__device__ __forceinline__ void cpa4(uint32_t s, const void* g) {
    asm volatile("cp.async.ca.shared.global [%0], [%1], 4;"
                 :: "r"(s), "l"(g) : "memory");
}
__device__ __forceinline__ void cpcommit() {
    asm volatile("cp.async.commit_group;" ::: "memory");
}
template <int N>
__device__ __forceinline__ void cpwait() {
    asm volatile("cp.async.wait_group %0;" :: "n"(N) : "memory");
}

// ===========================================================================
// Legacy bf16x3 GEMM (R5/R9-exact)
// ===========================================================================
#define TBM 128
#define TBK 16
#define XSTR 12
#define PLANE (TBM * XSTR)

__global__ __launch_bounds__(256) void gemm_bf16x3(
    const float* __restrict__ A, const float* __restrict__ B,
    const float* __restrict__ bias, float* __restrict__ C,
    int M, int N, int K, int act)
{
    __shared__ __align__(16) unsigned As[2][2 * PLANE];
    __shared__ __align__(16) unsigned Bs[2][2 * PLANE];

    int tid  = threadIdx.x;
    int lane = tid & 31;
    int warp = tid >> 5;
    int wm = warp >> 1, wn = warp & 1;
    int bm = blockIdx.y * TBM;
    int bn = blockIdx.x * 128;

    int arow = tid >> 1, ah = tid & 1;
    const float* Aptr = A + (size_t)(bm + arow) * K + ah * 8;
    int xa = (arow & 3) ^ ((arow >> 3) & 3);
    int ast_base = arow * XSTR + 4 * ah;
    int bnn = tid & 127, bh2 = tid >> 7;
    int gcol = bn + bnn;
    int xb = (bnn & 3) ^ ((bnn >> 3) & 3);
    int bst_base = bnn * XSTR + 4 * bh2;

    int fg = lane >> 2, ft = lane & 3;
    int idxA[2][2];
#pragma unroll
    for (int i = 0; i < 2; i++)
#pragma unroll
        for (int d = 0; d < 2; d++) {
            int row = wm * 32 + i * 16 + d * 8 + fg;
            idxA[i][d] = row * XSTR + (ft ^ (row & 3) ^ ((row >> 3) & 3));
        }
    int idxB[8];
#pragma unroll
    for (int j = 0; j < 8; j++) {
        int n = wn * 64 + j * 8 + fg;
        idxB[j] = n * XSTR + (ft ^ (n & 3) ^ ((n >> 3) & 3));
    }

    float acc[2][8][4];
#pragma unroll
    for (int i = 0; i < 2; i++)
#pragma unroll
        for (int j = 0; j < 8; j++)
#pragma unroll
            for (int l = 0; l < 4; l++) acc[i][j][l] = 0.f;

    {
        float4 f0 = *(const float4*)Aptr;
        float4 f1 = *(const float4*)(Aptr + 4);
        unsigned hi, lo;
        split2(f0.x, f0.y, hi, lo);
        As[0][ast_base + (0 ^ xa)] = hi; As[0][PLANE + ast_base + (0 ^ xa)] = lo;
        split2(f0.z, f0.w, hi, lo);
        As[0][ast_base + (1 ^ xa)] = hi; As[0][PLANE + ast_base + (1 ^ xa)] = lo;
        split2(f1.x, f1.y, hi, lo);
        As[0][ast_base + (2 ^ xa)] = hi; As[0][PLANE + ast_base + (2 ^ xa)] = lo;
        split2(f1.z, f1.w, hi, lo);
        As[0][ast_base + (3 ^ xa)] = hi; As[0][PLANE + ast_base + (3 ^ xa)] = lo;
#pragma unroll
        for (int i = 0; i < 4; i++) {
            int k = 8 * bh2 + 2 * i;
            float b0 = (gcol < N) ? B[(size_t)k * N + gcol] : 0.f;
            float b1 = (gcol < N) ? B[(size_t)(k + 1) * N + gcol] : 0.f;
            split2(b0, b1, hi, lo);
            Bs[0][bst_base + (i ^ xb)] = hi;
            Bs[0][PLANE + bst_base + (i ^ xb)] = lo;
        }
    }
    __syncthreads();

    int iters = K / TBK;
    for (int it = 1; it <= iters; it++) {
        bool has = (it < iters);
        float4 f0, f1;
        float bg[8];
        if (has) {
            int k0 = it * TBK;
            f0 = *(const float4*)(Aptr + k0);
            f1 = *(const float4*)(Aptr + k0 + 4);
#pragma unroll
            for (int i = 0; i < 4; i++) {
                int k = k0 + 8 * bh2 + 2 * i;
                bg[2 * i]     = (gcol < N) ? B[(size_t)k * N + gcol] : 0.f;
                bg[2 * i + 1] = (gcol < N) ? B[(size_t)(k + 1) * N + gcol] : 0.f;
            }
        }
        {
            const unsigned* Ab = As[(it - 1) & 1];
            const unsigned* Bb = Bs[(it - 1) & 1];
            unsigned ahf[2][4], alf[2][4];
#pragma unroll
            for (int i = 0; i < 2; i++) {
                ahf[i][0] = Ab[idxA[i][0]];
                ahf[i][1] = Ab[idxA[i][1]];
                ahf[i][2] = Ab[idxA[i][0] + 4];
                ahf[i][3] = Ab[idxA[i][1] + 4];
                alf[i][0] = Ab[PLANE + idxA[i][0]];
                alf[i][1] = Ab[PLANE + idxA[i][1]];
                alf[i][2] = Ab[PLANE + idxA[i][0] + 4];
                alf[i][3] = Ab[PLANE + idxA[i][1] + 4];
            }
#pragma unroll
            for (int j = 0; j < 8; j++) {
                unsigned bh0 = Bb[idxB[j]];
                unsigned bh1 = Bb[idxB[j] + 4];
                unsigned bl0 = Bb[PLANE + idxB[j]];
                unsigned bl1 = Bb[PLANE + idxB[j] + 4];
                mma_bf16(acc[0][j], ahf[0], bh0, bh1);
                mma_bf16(acc[1][j], ahf[1], bh0, bh1);
                mma_bf16(acc[0][j], ahf[0], bl0, bl1);
                mma_bf16(acc[1][j], ahf[1], bl0, bl1);
                mma_bf16(acc[0][j], alf[0], bh0, bh1);
                mma_bf16(acc[1][j], alf[1], bh0, bh1);
            }
        }
        if (has) {
            int buf = it & 1;
            unsigned hi, lo;
            split2(f0.x, f0.y, hi, lo);
            As[buf][ast_base + (0 ^ xa)] = hi; As[buf][PLANE + ast_base + (0 ^ xa)] = lo;
            split2(f0.z, f0.w, hi, lo);
            As[buf][ast_base + (1 ^ xa)] = hi; As[buf][PLANE + ast_base + (1 ^ xa)] = lo;
            split2(f1.x, f1.y, hi, lo);
            As[buf][ast_base + (2 ^ xa)] = hi; As[buf][PLANE + ast_base + (2 ^ xa)] = lo;
            split2(f1.z, f1.w, hi, lo);
            As[buf][ast_base + (3 ^ xa)] = hi; As[buf][PLANE + ast_base + (3 ^ xa)] = lo;
#pragma unroll
            for (int i = 0; i < 4; i++) {
                split2(bg[2 * i], bg[2 * i + 1], hi, lo);
                Bs[buf][bst_base + (i ^ xb)] = hi;
                Bs[buf][PLANE + bst_base + (i ^ xb)] = lo;
            }
        }
        __syncthreads();
    }

#pragma unroll
    for (int i = 0; i < 2; i++) {
        int row = bm + wm * 32 + i * 16 + fg;
#pragma unroll
        for (int j = 0; j < 8; j++) {
            int col = bn + wn * 64 + j * 8 + ft * 2;
            if (col < N) {
                float b0 = bias[col], b1 = bias[col + 1];
                float v0 = acc[i][j][0] + b0;
                float v1 = acc[i][j][1] + b1;
                float v2 = acc[i][j][2] + b0;
                float v3 = acc[i][j][3] + b1;
                if (act == 1) {
                    v0 = v0 / (1.f + __expf(-v0));
                    v1 = v1 / (1.f + __expf(-v1));
                    v2 = v2 / (1.f + __expf(-v2));
                    v3 = v3 / (1.f + __expf(-v3));
                }
                *(float2*)&C[(size_t)row * N + col] = make_float2(v0, v1);
                *(float2*)&C[(size_t)(row + 8) * N + col] = make_float2(v2, v3);
            }
        }
    }
}

// ===========================================================================
// Scan v4: 2-step chunked (micro-WY). Exact algebra:
//   e1 = n1*(c0a*dk1 - c1a*v1);              y1 = c2a*dq1
//   e2 = n2*(a1*c0b*dk2 + e1*gkk - c1b*v2);  y2 = a1*c2b*dq2 + e1*gkq
//   gkk = c0a*c0b*sum(k1*k2); gkq = c0a*c2b*sum(k1*q2)
//   m   = (a1*a2)*m + (a2*e1*c0a)*k1 + (e2*c0b)*k2
// One shfl-reduction wave (6 values) per 2 steps instead of 2 waves.
// cp.async ring SDEPTH=8, 2 stages/iter, wait_group<6>.
// ===========================================================================
#define SDEPTH 8
#define SBUF 224

__global__ __launch_bounds__(128) void scan_kernel(
    const float* __restrict__ base,    // [B,S,H,3,HD]
    const float* __restrict__ ctrl,    // [B,S,H,5]
    const float* __restrict__ memory0, // [B,H,HD,HD]
    float* __restrict__ ys,            // [B,S,D]
    float* __restrict__ mfinal)        // [B,H,HD,HD]
{
    __shared__ __align__(16) float sbuf[SDEPTH][SBUF];

    int bh   = blockIdx.x >> 1;
    int half = blockIdx.x & 1;
    int b = bh >> 4, h = bh & 15;
    int tid = threadIdx.x;
    int r = (tid >> 2) + half * 32;
    int g = tid & 3;

    float m[16];
    {
        const float* M0 = memory0 + (((size_t)bh * HDIM + r) * HDIM + g * 16);
#pragma unroll
        for (int jj = 0; jj < 16; jj++) m[jj] = M0[jj];
    }

    const float* bsrc = base + ((size_t)b * SS * HH + h) * 192;
    const float* csrc = ctrl + (size_t)b * SS * 80 + h * 5;
    float* yptr = ys + (size_t)b * SS * DD + h * HDIM + r;

    unsigned sb_addr[SDEPTH];
#pragma unroll
    for (int d = 0; d < SDEPTH; d++)
        sb_addr[d] = (unsigned)__cvta_generic_to_shared(&sbuf[d][0]);

#define SCAN_ISSUE(st) do {                                              \
        unsigned sa_ = sb_addr[(st) & (SDEPTH - 1)];                     \
        if (tid < 48)                                                    \
            cpa16(sa_ + tid * 16, bsrc + (size_t)(st) * 3072 + tid * 4); \
        else if (tid < 53)                                               \
            cpa4(sa_ + 768 + (tid - 48) * 4,                             \
                 csrc + (size_t)(st) * 80 + (tid - 48));                 \
        cpcommit();                                                      \
    } while (0)

    // prologue: stages 0..5 (6 groups)
#pragma unroll
    for (int p = 0; p < 6; p++) SCAN_ISSUE(p);

    for (int s = 0; s < SS; s += 2) {
        // issue stages s+6, s+7 (always exactly 2 commits/iter)
        if (s + 6 < SS) SCAN_ISSUE(s + 6); else cpcommit();
        if (s + 7 < SS) SCAN_ISSUE(s + 7); else cpcommit();
        cpwait<6>();         // stages s and s+1 complete
        __syncthreads();

        const float* s1 = sbuf[s & (SDEPTH - 1)];
        const float* s2 = sbuf[(s + 1) & (SDEPTH - 1)];

        float c0a = s1[192], c1a = s1[193], c2a = s1[194];
        float c0b = s2[192], c1b = s2[193], c2b = s2[194];
        float n1 = 1.f / (1.f + __expf(-s1[195]));
        float a1 = 1.f / (1.f + __expf(-s1[196]));
        float n2 = 1.f / (1.f + __expf(-s2[195]));
        float a2 = 1.f / (1.f + __expf(-s2[196]));
        float v1 = s1[64 + r], v2 = s2[64 + r];

        float kr1[16], qr1[16], kr2[16], qr2[16];
#pragma unroll
        for (int w = 0; w < 4; w++) {
            *(float4*)&kr1[w * 4] = *(const float4*)&s1[g * 16 + w * 4];
            *(float4*)&qr1[w * 4] = *(const float4*)&s1[128 + g * 16 + w * 4];
            *(float4*)&kr2[w * 4] = *(const float4*)&s2[g * 16 + w * 4];
            *(float4*)&qr2[w * 4] = *(const float4*)&s2[128 + g * 16 + w * 4];
        }

        // 6 partial sums over this thread's 16 columns (2-way split each)
        float dk1a = 0.f, dk1b = 0.f, dq1a = 0.f, dq1b = 0.f;
        float dk2a = 0.f, dk2b = 0.f, dq2a = 0.f, dq2b = 0.f;
        float gka = 0.f, gkb = 0.f, gqa = 0.f, gqb = 0.f;
#pragma unroll
        for (int jj = 0; jj < 16; jj += 2) {
            dk1a += m[jj] * kr1[jj];       dk1b += m[jj + 1] * kr1[jj + 1];
            dq1a += m[jj] * qr1[jj];       dq1b += m[jj + 1] * qr1[jj + 1];
            dk2a += m[jj] * kr2[jj];       dk2b += m[jj + 1] * kr2[jj + 1];
            dq2a += m[jj] * qr2[jj];       dq2b += m[jj + 1] * qr2[jj + 1];
            gka  += kr1[jj] * kr2[jj];     gkb  += kr1[jj + 1] * kr2[jj + 1];
            gqa  += kr1[jj] * qr2[jj];     gqb  += kr1[jj + 1] * qr2[jj + 1];
        }
        float dk1 = dk1a + dk1b, dq1 = dq1a + dq1b;
        float dk2 = dk2a + dk2b, dq2 = dq2a + dq2b;
        float gk  = gka + gkb,   gq  = gqa + gqb;

        // one reduction wave: 6 independent values, xor 1 then xor 2
        dk1 += __shfl_xor_sync(0xffffffffu, dk1, 1);
        dq1 += __shfl_xor_sync(0xffffffffu, dq1, 1);
        dk2 += __shfl_xor_sync(0xffffffffu, dk2, 1);
        dq2 += __shfl_xor_sync(0xffffffffu, dq2, 1);
        gk  += __shfl_xor_sync(0xffffffffu, gk, 1);
        gq  += __shfl_xor_sync(0xffffffffu, gq, 1);
        dk1 += __shfl_xor_sync(0xffffffffu, dk1, 2);
        dq1 += __shfl_xor_sync(0xffffffffu, dq1, 2);
        dk2 += __shfl_xor_sync(0xffffffffu, dk2, 2);
        dq2 += __shfl_xor_sync(0xffffffffu, dq2, 2);
        gk  += __shfl_xor_sync(0xffffffffu, gk, 2);
        gq  += __shfl_xor_sync(0xffffffffu, gq, 2);

        // substitution (scalar per row)
        float e1 = n1 * (c0a * dk1 - c1a * v1);
        float y1 = c2a * dq1;
        float gkk = c0a * c0b * gk;
        float gkq = c0a * c2b * gq;
        float e2 = n2 * (a1 * c0b * dk2 + e1 * gkk - c1b * v2);
        float y2 = a1 * c2b * dq2 + e1 * gkq;

        if (g == 0) {
            yptr[(size_t)s * DD] = y1;
            yptr[(size_t)(s + 1) * DD] = y2;
        }

        // fused update
        float a12 = a1 * a2;
        float w1 = a2 * e1 * c0a;
        float w2 = e2 * c0b;
#pragma unroll
        for (int jj = 0; jj < 16; jj++)
            m[jj] = a12 * m[jj] + w1 * kr1[jj] + w2 * kr2[jj];

        __syncthreads();   // reads of stages s, s+1 done before slot reuse
    }

    float* MF = mfinal + (((size_t)bh * HDIM + r) * HDIM + g * 16);
#pragma unroll
    for (int jj = 0; jj < 16; jj++) MF[jj] = m[jj];
}

// ===========================================================================
extern "C" void kernel_launch(void* const* d_in, const int* in_sizes, int n_in,
                              void* d_out, int out_size)
{
    (void)in_sizes; (void)n_in;
    const float* x       = (const float*)d_in[0];
    const float* memory0 = (const float*)d_in[1];
    const float* W_in    = (const float*)d_in[2];
    const float* b_in    = (const float*)d_in[3];
    const float* Wc1     = (const float*)d_in[4];
    const float* bc1     = (const float*)d_in[5];
    const float* Wc2     = (const float*)d_in[6];
    const float* bc2     = (const float*)d_in[7];
    const float* W_out   = (const float*)d_in[8];
    const float* b_out   = (const float*)d_in[9];

    float* out = (float*)d_out;

    float *base, *hidden, *ctrl, *ys, *mf_scratch;
    cudaGetSymbolAddress((void**)&base,       g_base);
    cudaGetSymbolAddress((void**)&hidden,     g_hidden);
    cudaGetSymbolAddress((void**)&ctrl,       g_ctrl);
    cudaGetSymbolAddress((void**)&ys,         g_ys);
    cudaGetSymbolAddress((void**)&mf_scratch, g_mf);

    const size_t OUT_ELEMS = (size_t)MR * DD;
    const size_t MF_ELEMS  = (size_t)BB * HH * HDIM * HDIM;
    float* mfinal = ((size_t)out_size >= OUT_ELEMS + MF_ELEMS)
                        ? (out + OUT_ELEMS) : mf_scratch;

    // base = x @ W_in + b_in                  [8192,3072]
    gemm_bf16x3<<<dim3(3 * DD / 128, MR / TBM), 256>>>(
        x, W_in, b_in, base, MR, 3 * DD, DD, 0);
    // hidden = silu(x @ Wc1 + bc1)            [8192,1024]
    gemm_bf16x3<<<dim3(DD / 128, MR / TBM), 256>>>(
        x, Wc1, bc1, hidden, MR, DD, DD, 1);
    // ctrl = hidden @ Wc2 + bc2               [8192,80]
    gemm_bf16x3<<<dim3(1, MR / TBM), 256>>>(
        hidden, Wc2, bc2, ctrl, MR, 5 * HH, DD, 0);
    // sequential scan (2-step chunked)
    scan_kernel<<<BB * HH * 2, 128>>>(base, ctrl, memory0, ys, mfinal);
    // out = ys @ W_out + b_out                [8192,1024]
    gemm_bf16x3<<<dim3(DD / 128, MR / TBM), 256>>>(
        ys, W_out, b_out, out, MR, DD, DD, 0);
}

// round 12
// speedup vs baseline: 1.3261x; 1.0356x over previous
#include <cuda_runtime.h>
#include <cuda_bf16.h>
#include <math.h>
#include <stdint.h>

#define BB 4
#define SS 2048
#define DD 1024
#define HH 16
#define HDIM 64
#define MR (BB * SS)   // 8192

// ---- scratch (device globals: allocation-free per harness rules) ----
__device__ float g_base[(size_t)MR * 3 * DD];      // [8192,3072]
__device__ float g_hidden[(size_t)MR * DD];        // [8192,1024]
__device__ float g_ctrl[(size_t)MR * 80 + 16];     // [8192,80] (+pad)
__device__ float g_ys[(size_t)MR * DD];            // [8192,1024]
__device__ float g_mf[(size_t)BB * HH * HDIM * HDIM];

// ---- second stream + fork/join events, created at module load (pre-main,
// outside any graph capture; no device-memory allocation involved) ----
struct HxStreams {
    cudaStream_t s2;
    cudaEvent_t e1, e2;
    HxStreams() {
        cudaStreamCreateWithFlags(&s2, cudaStreamNonBlocking);
        cudaEventCreateWithFlags(&e1, cudaEventDisableTiming);
        cudaEventCreateWithFlags(&e2, cudaEventDisableTiming);
    }
};
static HxStreams g_hx;

// ===========================================================================
// helpers
// ===========================================================================
__device__ __forceinline__ void split2(float a0, float a1,
                                       unsigned& hi, unsigned& lo) {
    asm("cvt.rn.bf16x2.f32 %0, %1, %2;" : "=r"(hi) : "f"(a1), "f"(a0));
    float h0 = __uint_as_float(hi << 16);
    float h1 = __uint_as_float(hi & 0xffff0000u);
    float r0 = a0 - h0, r1 = a1 - h1;
    asm("cvt.rn.bf16x2.f32 %0, %1, %2;" : "=r"(lo) : "f"(r1), "f"(r0));
}

__device__ __forceinline__ void mma_bf16(float* c, const unsigned* a,
                                         unsigned b0, unsigned b1) {
    asm volatile(
        "mma.sync.aligned.m16n8k16.row.col.f32.bf16.bf16.f32 "
        "{%0,%1,%2,%3}, {%4,%5,%6,%7}, {%8,%9}, {%0,%1,%2,%3};"
        : "+f"(c[0]), "+f"(c[1]), "+f"(c[2]), "+f"(c[3])
        : "r"(a[0]), "r"(a[1]), "r"(a[2]), "r"(a[3]), "r"(b0), "r"(b1));
}

__device__ __forceinline__ void cpa16(uint32_t s, const void* g) {
    asm volatile("cp.async.ca.shared.global [%0], [%1], 16;"
                 :: "r"(s), "l"(g) : "memory");
}
__device__ __forceinline__ void cpa4(uint32_t s, const void* g) {
    asm volatile("cp.async.ca.shared.global [%0], [%1], 4;"
                 :: "r"(s), "l"(g) : "memory");
}
__device__ __forceinline__ void cpcommit() {
    asm volatile("cp.async.commit_group;" ::: "memory");
}
template <int N>
__device__ __forceinline__ void cpwait() {
    asm volatile("cp.async.wait_group %0;" :: "n"(N) : "memory");
}

// ===========================================================================
// Legacy bf16x3 GEMM (R5/R9/R11-exact)
// ===========================================================================
#define TBM 128
#define TBK 16
#define XSTR 12
#define PLANE (TBM * XSTR)

__global__ __launch_bounds__(256) void gemm_bf16x3(
    const float* __restrict__ A, const float* __restrict__ B,
    const float* __restrict__ bias, float* __restrict__ C,
    int M, int N, int K, int act)
{
    __shared__ __align__(16) unsigned As[2][2 * PLANE];
    __shared__ __align__(16) unsigned Bs[2][2 * PLANE];

    int tid  = threadIdx.x;
    int lane = tid & 31;
    int warp = tid >> 5;
    int wm = warp >> 1, wn = warp & 1;
    int bm = blockIdx.y * TBM;
    int bn = blockIdx.x * 128;

    int arow = tid >> 1, ah = tid & 1;
    const float* Aptr = A + (size_t)(bm + arow) * K + ah * 8;
    int xa = (arow & 3) ^ ((arow >> 3) & 3);
    int ast_base = arow * XSTR + 4 * ah;
    int bnn = tid & 127, bh2 = tid >> 7;
    int gcol = bn + bnn;
    int xb = (bnn & 3) ^ ((bnn >> 3) & 3);
    int bst_base = bnn * XSTR + 4 * bh2;

    int fg = lane >> 2, ft = lane & 3;
    int idxA[2][2];
#pragma unroll
    for (int i = 0; i < 2; i++)
#pragma unroll
        for (int d = 0; d < 2; d++) {
            int row = wm * 32 + i * 16 + d * 8 + fg;
            idxA[i][d] = row * XSTR + (ft ^ (row & 3) ^ ((row >> 3) & 3));
        }
    int idxB[8];
#pragma unroll
    for (int j = 0; j < 8; j++) {
        int n = wn * 64 + j * 8 + fg;
        idxB[j] = n * XSTR + (ft ^ (n & 3) ^ ((n >> 3) & 3));
    }

    float acc[2][8][4];
#pragma unroll
    for (int i = 0; i < 2; i++)
#pragma unroll
        for (int j = 0; j < 8; j++)
#pragma unroll
            for (int l = 0; l < 4; l++) acc[i][j][l] = 0.f;

    {
        float4 f0 = *(const float4*)Aptr;
        float4 f1 = *(const float4*)(Aptr + 4);
        unsigned hi, lo;
        split2(f0.x, f0.y, hi, lo);
        As[0][ast_base + (0 ^ xa)] = hi; As[0][PLANE + ast_base + (0 ^ xa)] = lo;
        split2(f0.z, f0.w, hi, lo);
        As[0][ast_base + (1 ^ xa)] = hi; As[0][PLANE + ast_base + (1 ^ xa)] = lo;
        split2(f1.x, f1.y, hi, lo);
        As[0][ast_base + (2 ^ xa)] = hi; As[0][PLANE + ast_base + (2 ^ xa)] = lo;
        split2(f1.z, f1.w, hi, lo);
        As[0][ast_base + (3 ^ xa)] = hi; As[0][PLANE + ast_base + (3 ^ xa)] = lo;
#pragma unroll
        for (int i = 0; i < 4; i++) {
            int k = 8 * bh2 + 2 * i;
            float b0 = (gcol < N) ? B[(size_t)k * N + gcol] : 0.f;
            float b1 = (gcol < N) ? B[(size_t)(k + 1) * N + gcol] : 0.f;
            split2(b0, b1, hi, lo);
            Bs[0][bst_base + (i ^ xb)] = hi;
            Bs[0][PLANE + bst_base + (i ^ xb)] = lo;
        }
    }
    __syncthreads();

    int iters = K / TBK;
    for (int it = 1; it <= iters; it++) {
        bool has = (it < iters);
        float4 f0, f1;
        float bg[8];
        if (has) {
            int k0 = it * TBK;
            f0 = *(const float4*)(Aptr + k0);
            f1 = *(const float4*)(Aptr + k0 + 4);
#pragma unroll
            for (int i = 0; i < 4; i++) {
                int k = k0 + 8 * bh2 + 2 * i;
                bg[2 * i]     = (gcol < N) ? B[(size_t)k * N + gcol] : 0.f;
                bg[2 * i + 1] = (gcol < N) ? B[(size_t)(k + 1) * N + gcol] : 0.f;
            }
        }
        {
            const unsigned* Ab = As[(it - 1) & 1];
            const unsigned* Bb = Bs[(it - 1) & 1];
            unsigned ahf[2][4], alf[2][4];
#pragma unroll
            for (int i = 0; i < 2; i++) {
                ahf[i][0] = Ab[idxA[i][0]];
                ahf[i][1] = Ab[idxA[i][1]];
                ahf[i][2] = Ab[idxA[i][0] + 4];
                ahf[i][3] = Ab[idxA[i][1] + 4];
                alf[i][0] = Ab[PLANE + idxA[i][0]];
                alf[i][1] = Ab[PLANE + idxA[i][1]];
                alf[i][2] = Ab[PLANE + idxA[i][0] + 4];
                alf[i][3] = Ab[PLANE + idxA[i][1] + 4];
            }
#pragma unroll
            for (int j = 0; j < 8; j++) {
                unsigned bh0 = Bb[idxB[j]];
                unsigned bh1 = Bb[idxB[j] + 4];
                unsigned bl0 = Bb[PLANE + idxB[j]];
                unsigned bl1 = Bb[PLANE + idxB[j] + 4];
                mma_bf16(acc[0][j], ahf[0], bh0, bh1);
                mma_bf16(acc[1][j], ahf[1], bh0, bh1);
                mma_bf16(acc[0][j], ahf[0], bl0, bl1);
                mma_bf16(acc[1][j], ahf[1], bl0, bl1);
                mma_bf16(acc[0][j], alf[0], bh0, bh1);
                mma_bf16(acc[1][j], alf[1], bh0, bh1);
            }
        }
        if (has) {
            int buf = it & 1;
            unsigned hi, lo;
            split2(f0.x, f0.y, hi, lo);
            As[buf][ast_base + (0 ^ xa)] = hi; As[buf][PLANE + ast_base + (0 ^ xa)] = lo;
            split2(f0.z, f0.w, hi, lo);
            As[buf][ast_base + (1 ^ xa)] = hi; As[buf][PLANE + ast_base + (1 ^ xa)] = lo;
            split2(f1.x, f1.y, hi, lo);
            As[buf][ast_base + (2 ^ xa)] = hi; As[buf][PLANE + ast_base + (2 ^ xa)] = lo;
            split2(f1.z, f1.w, hi, lo);
            As[buf][ast_base + (3 ^ xa)] = hi; As[buf][PLANE + ast_base + (3 ^ xa)] = lo;
#pragma unroll
            for (int i = 0; i < 4; i++) {
                split2(bg[2 * i], bg[2 * i + 1], hi, lo);
                Bs[buf][bst_base + (i ^ xb)] = hi;
                Bs[buf][PLANE + bst_base + (i ^ xb)] = lo;
            }
        }
        __syncthreads();
    }

#pragma unroll
    for (int i = 0; i < 2; i++) {
        int row = bm + wm * 32 + i * 16 + fg;
#pragma unroll
        for (int j = 0; j < 8; j++) {
            int col = bn + wn * 64 + j * 8 + ft * 2;
            if (col < N) {
                float b0 = bias[col], b1 = bias[col + 1];
                float v0 = acc[i][j][0] + b0;
                float v1 = acc[i][j][1] + b1;
                float v2 = acc[i][j][2] + b0;
                float v3 = acc[i][j][3] + b1;
                if (act == 1) {
                    v0 = v0 / (1.f + __expf(-v0));
                    v1 = v1 / (1.f + __expf(-v1));
                    v2 = v2 / (1.f + __expf(-v2));
                    v3 = v3 / (1.f + __expf(-v3));
                }
                *(float2*)&C[(size_t)row * N + col] = make_float2(v0, v1);
                *(float2*)&C[(size_t)(row + 8) * N + col] = make_float2(v2, v3);
            }
        }
    }
}

// ===========================================================================
// Scan v4 (R11-exact): 2-step chunked micro-WY
// ===========================================================================
#define SDEPTH 8
#define SBUF 224

__global__ __launch_bounds__(128) void scan_kernel(
    const float* __restrict__ base,    // [B,S,H,3,HD]
    const float* __restrict__ ctrl,    // [B,S,H,5]
    const float* __restrict__ memory0, // [B,H,HD,HD]
    float* __restrict__ ys,            // [B,S,D]
    float* __restrict__ mfinal)        // [B,H,HD,HD]
{
    __shared__ __align__(16) float sbuf[SDEPTH][SBUF];

    int bh   = blockIdx.x >> 1;
    int half = blockIdx.x & 1;
    int b = bh >> 4, h = bh & 15;
    int tid = threadIdx.x;
    int r = (tid >> 2) + half * 32;
    int g = tid & 3;

    float m[16];
    {
        const float* M0 = memory0 + (((size_t)bh * HDIM + r) * HDIM + g * 16);
#pragma unroll
        for (int jj = 0; jj < 16; jj++) m[jj] = M0[jj];
    }

    const float* bsrc = base + ((size_t)b * SS * HH + h) * 192;
    const float* csrc = ctrl + (size_t)b * SS * 80 + h * 5;
    float* yptr = ys + (size_t)b * SS * DD + h * HDIM + r;

    unsigned sb_addr[SDEPTH];
#pragma unroll
    for (int d = 0; d < SDEPTH; d++)
        sb_addr[d] = (unsigned)__cvta_generic_to_shared(&sbuf[d][0]);

#define SCAN_ISSUE(st) do {                                              \
        unsigned sa_ = sb_addr[(st) & (SDEPTH - 1)];                     \
        if (tid < 48)                                                    \
            cpa16(sa_ + tid * 16, bsrc + (size_t)(st) * 3072 + tid * 4); \
        else if (tid < 53)                                               \
            cpa4(sa_ + 768 + (tid - 48) * 4,                             \
                 csrc + (size_t)(st) * 80 + (tid - 48));                 \
        cpcommit();                                                      \
    } while (0)

    // prologue: stages 0..5 (6 groups)
#pragma unroll
    for (int p = 0; p < 6; p++) SCAN_ISSUE(p);

    for (int s = 0; s < SS; s += 2) {
        if (s + 6 < SS) SCAN_ISSUE(s + 6); else cpcommit();
        if (s + 7 < SS) SCAN_ISSUE(s + 7); else cpcommit();
        cpwait<6>();         // stages s and s+1 complete
        __syncthreads();

        const float* s1 = sbuf[s & (SDEPTH - 1)];
        const float* s2 = sbuf[(s + 1) & (SDEPTH - 1)];

        float c0a = s1[192], c1a = s1[193], c2a = s1[194];
        float c0b = s2[192], c1b = s2[193], c2b = s2[194];
        float n1 = 1.f / (1.f + __expf(-s1[195]));
        float a1 = 1.f / (1.f + __expf(-s1[196]));
        float n2 = 1.f / (1.f + __expf(-s2[195]));
        float a2 = 1.f / (1.f + __expf(-s2[196]));
        float v1 = s1[64 + r], v2 = s2[64 + r];

        float kr1[16], qr1[16], kr2[16], qr2[16];
#pragma unroll
        for (int w = 0; w < 4; w++) {
            *(float4*)&kr1[w * 4] = *(const float4*)&s1[g * 16 + w * 4];
            *(float4*)&qr1[w * 4] = *(const float4*)&s1[128 + g * 16 + w * 4];
            *(float4*)&kr2[w * 4] = *(const float4*)&s2[g * 16 + w * 4];
            *(float4*)&qr2[w * 4] = *(const float4*)&s2[128 + g * 16 + w * 4];
        }

        float dk1a = 0.f, dk1b = 0.f, dq1a = 0.f, dq1b = 0.f;
        float dk2a = 0.f, dk2b = 0.f, dq2a = 0.f, dq2b = 0.f;
        float gka = 0.f, gkb = 0.f, gqa = 0.f, gqb = 0.f;
#pragma unroll
        for (int jj = 0; jj < 16; jj += 2) {
            dk1a += m[jj] * kr1[jj];       dk1b += m[jj + 1] * kr1[jj + 1];
            dq1a += m[jj] * qr1[jj];       dq1b += m[jj + 1] * qr1[jj + 1];
            dk2a += m[jj] * kr2[jj];       dk2b += m[jj + 1] * kr2[jj + 1];
            dq2a += m[jj] * qr2[jj];       dq2b += m[jj + 1] * qr2[jj + 1];
            gka  += kr1[jj] * kr2[jj];     gkb  += kr1[jj + 1] * kr2[jj + 1];
            gqa  += kr1[jj] * qr2[jj];     gqb  += kr1[jj + 1] * qr2[jj + 1];
        }
        float dk1 = dk1a + dk1b, dq1 = dq1a + dq1b;
        float dk2 = dk2a + dk2b, dq2 = dq2a + dq2b;
        float gk  = gka + gkb,   gq  = gqa + gqb;

        dk1 += __shfl_xor_sync(0xffffffffu, dk1, 1);
        dq1 += __shfl_xor_sync(0xffffffffu, dq1, 1);
        dk2 += __shfl_xor_sync(0xffffffffu, dk2, 1);
        dq2 += __shfl_xor_sync(0xffffffffu, dq2, 1);
        gk  += __shfl_xor_sync(0xffffffffu, gk, 1);
        gq  += __shfl_xor_sync(0xffffffffu, gq, 1);
        dk1 += __shfl_xor_sync(0xffffffffu, dk1, 2);
        dq1 += __shfl_xor_sync(0xffffffffu, dq1, 2);
        dk2 += __shfl_xor_sync(0xffffffffu, dk2, 2);
        dq2 += __shfl_xor_sync(0xffffffffu, dq2, 2);
        gk  += __shfl_xor_sync(0xffffffffu, gk, 2);
        gq  += __shfl_xor_sync(0xffffffffu, gq, 2);

        float e1 = n1 * (c0a * dk1 - c1a * v1);
        float y1 = c2a * dq1;
        float gkk = c0a * c0b * gk;
        float gkq = c0a * c2b * gq;
        float e2 = n2 * (a1 * c0b * dk2 + e1 * gkk - c1b * v2);
        float y2 = a1 * c2b * dq2 + e1 * gkq;

        if (g == 0) {
            yptr[(size_t)s * DD] = y1;
            yptr[(size_t)(s + 1) * DD] = y2;
        }

        float a12 = a1 * a2;
        float w1 = a2 * e1 * c0a;
        float w2 = e2 * c0b;
#pragma unroll
        for (int jj = 0; jj < 16; jj++)
            m[jj] = a12 * m[jj] + w1 * kr1[jj] + w2 * kr2[jj];

        __syncthreads();
    }

    float* MF = mfinal + (((size_t)bh * HDIM + r) * HDIM + g * 16);
#pragma unroll
    for (int jj = 0; jj < 16; jj++) MF[jj] = m[jj];
}

// ===========================================================================
extern "C" void kernel_launch(void* const* d_in, const int* in_sizes, int n_in,
                              void* d_out, int out_size)
{
    (void)in_sizes; (void)n_in;
    const float* x       = (const float*)d_in[0];
    const float* memory0 = (const float*)d_in[1];
    const float* W_in    = (const float*)d_in[2];
    const float* b_in    = (const float*)d_in[3];
    const float* Wc1     = (const float*)d_in[4];
    const float* bc1     = (const float*)d_in[5];
    const float* Wc2     = (const float*)d_in[6];
    const float* bc2     = (const float*)d_in[7];
    const float* W_out   = (const float*)d_in[8];
    const float* b_out   = (const float*)d_in[9];

    float* out = (float*)d_out;

    float *base, *hidden, *ctrl, *ys, *mf_scratch;
    cudaGetSymbolAddress((void**)&base,       g_base);
    cudaGetSymbolAddress((void**)&hidden,     g_hidden);
    cudaGetSymbolAddress((void**)&ctrl,       g_ctrl);
    cudaGetSymbolAddress((void**)&ys,         g_ys);
    cudaGetSymbolAddress((void**)&mf_scratch, g_mf);

    const size_t OUT_ELEMS = (size_t)MR * DD;
    const size_t MF_ELEMS  = (size_t)BB * HH * HDIM * HDIM;
    float* mfinal = ((size_t)out_size >= OUT_ELEMS + MF_ELEMS)
                        ? (out + OUT_ELEMS) : mf_scratch;

    // ---- fork: ctrl path (gemm2 -> gemm3) on s2, base gemm on main ----
    cudaEventRecord(g_hx.e1, 0);
    cudaStreamWaitEvent(g_hx.s2, g_hx.e1, 0);

    // hidden = silu(x @ Wc1 + bc1)   [s2]
    gemm_bf16x3<<<dim3(DD / 128, MR / TBM), 256, 0, g_hx.s2>>>(
        x, Wc1, bc1, hidden, MR, DD, DD, 1);
    // ctrl = hidden @ Wc2 + bc2      [s2]
    gemm_bf16x3<<<dim3(1, MR / TBM), 256, 0, g_hx.s2>>>(
        hidden, Wc2, bc2, ctrl, MR, 5 * HH, DD, 0);
    cudaEventRecord(g_hx.e2, g_hx.s2);

    // base = x @ W_in + b_in         [main stream, concurrent with s2]
    gemm_bf16x3<<<dim3(3 * DD / 128, MR / TBM), 256>>>(
        x, W_in, b_in, base, MR, 3 * DD, DD, 0);

    // ---- join: scan needs base (main) + ctrl (s2) ----
    cudaStreamWaitEvent((cudaStream_t)0, g_hx.e2, 0);

    // sequential scan (2-step chunked)
    scan_kernel<<<BB * HH * 2, 128>>>(base, ctrl, memory0, ys, mfinal);
    // out = ys @ W_out + b_out
    gemm_bf16x3<<<dim3(DD / 128, MR / TBM), 256>>>(
        ys, W_out, b_out, out, MR, DD, DD, 0);
}

// round 13
// speedup vs baseline: 1.3941x; 1.0513x over previous
#include <cuda_runtime.h>
#include <cuda_bf16.h>
#include <math.h>
#include <stdint.h>

#define BB 4
#define SS 2048
#define DD 1024
#define HH 16
#define HDIM 64
#define MR (BB * SS)   // 8192

// ---- scratch (device globals: allocation-free per harness rules) ----
__device__ float g_base[(size_t)MR * 3 * DD];      // [8192,3072]
__device__ float g_hidden[(size_t)MR * DD];        // [8192,1024]
__device__ float g_ctrl[(size_t)MR * 80 + 16];     // [8192,80] (+pad)
__device__ float g_ys[(size_t)MR * DD];            // [8192,1024]
__device__ float g_mf[(size_t)BB * HH * HDIM * HDIM];

// ---- second stream + fork/join events (module-load construction; outside
// graph capture, no device allocation) ----
struct HxStreams {
    cudaStream_t s2;
    cudaEvent_t e1, e2;
    HxStreams() {
        cudaStreamCreateWithFlags(&s2, cudaStreamNonBlocking);
        cudaEventCreateWithFlags(&e1, cudaEventDisableTiming);
        cudaEventCreateWithFlags(&e2, cudaEventDisableTiming);
    }
};
static HxStreams g_hx;

// ===========================================================================
// helpers
// ===========================================================================
__device__ __forceinline__ void split2(float a0, float a1,
                                       unsigned& hi, unsigned& lo) {
    asm("cvt.rn.bf16x2.f32 %0, %1, %2;" : "=r"(hi) : "f"(a1), "f"(a0));
    float h0 = __uint_as_float(hi << 16);
    float h1 = __uint_as_float(hi & 0xffff0000u);
    float r0 = a0 - h0, r1 = a1 - h1;
    asm("cvt.rn.bf16x2.f32 %0, %1, %2;" : "=r"(lo) : "f"(r1), "f"(r0));
}

__device__ __forceinline__ void mma_bf16(float* c, const unsigned* a,
                                         unsigned b0, unsigned b1) {
    asm volatile(
        "mma.sync.aligned.m16n8k16.row.col.f32.bf16.bf16.f32 "
        "{%0,%1,%2,%3}, {%4,%5,%6,%7}, {%8,%9}, {%0,%1,%2,%3};"
        : "+f"(c[0]), "+f"(c[1]), "+f"(c[2]), "+f"(c[3])
        : "r"(a[0]), "r"(a[1]), "r"(a[2]), "r"(a[3]), "r"(b0), "r"(b1));
}

__device__ __forceinline__ void cpa16(uint32_t s, const void* g) {
    asm volatile("cp.async.ca.shared.global [%0], [%1], 16;"
                 :: "r"(s), "l"(g) : "memory");
}
__device__ __forceinline__ void cpa4(uint32_t s, const void* g) {
    asm volatile("cp.async.ca.shared.global [%0], [%1], 4;"
                 :: "r"(s), "l"(g) : "memory");
}
__device__ __forceinline__ void cpcommit() {
    asm volatile("cp.async.commit_group;" ::: "memory");
}
template <int N>
__device__ __forceinline__ void cpwait() {
    asm volatile("cp.async.wait_group %0;" :: "n"(N) : "memory");
}

// ===========================================================================
// Legacy bf16x3 GEMM (R5/R9/R11/R12-exact)
// ===========================================================================
#define TBM 128
#define TBK 16
#define XSTR 12
#define PLANE (TBM * XSTR)

__global__ __launch_bounds__(256) void gemm_bf16x3(
    const float* __restrict__ A, const float* __restrict__ B,
    const float* __restrict__ bias, float* __restrict__ C,
    int M, int N, int K, int act)
{
    __shared__ __align__(16) unsigned As[2][2 * PLANE];
    __shared__ __align__(16) unsigned Bs[2][2 * PLANE];

    int tid  = threadIdx.x;
    int lane = tid & 31;
    int warp = tid >> 5;
    int wm = warp >> 1, wn = warp & 1;
    int bm = blockIdx.y * TBM;
    int bn = blockIdx.x * 128;

    int arow = tid >> 1, ah = tid & 1;
    const float* Aptr = A + (size_t)(bm + arow) * K + ah * 8;
    int xa = (arow & 3) ^ ((arow >> 3) & 3);
    int ast_base = arow * XSTR + 4 * ah;
    int bnn = tid & 127, bh2 = tid >> 7;
    int gcol = bn + bnn;
    int xb = (bnn & 3) ^ ((bnn >> 3) & 3);
    int bst_base = bnn * XSTR + 4 * bh2;

    int fg = lane >> 2, ft = lane & 3;
    int idxA[2][2];
#pragma unroll
    for (int i = 0; i < 2; i++)
#pragma unroll
        for (int d = 0; d < 2; d++) {
            int row = wm * 32 + i * 16 + d * 8 + fg;
            idxA[i][d] = row * XSTR + (ft ^ (row & 3) ^ ((row >> 3) & 3));
        }
    int idxB[8];
#pragma unroll
    for (int j = 0; j < 8; j++) {
        int n = wn * 64 + j * 8 + fg;
        idxB[j] = n * XSTR + (ft ^ (n & 3) ^ ((n >> 3) & 3));
    }

    float acc[2][8][4];
#pragma unroll
    for (int i = 0; i < 2; i++)
#pragma unroll
        for (int j = 0; j < 8; j++)
#pragma unroll
            for (int l = 0; l < 4; l++) acc[i][j][l] = 0.f;

    {
        float4 f0 = *(const float4*)Aptr;
        float4 f1 = *(const float4*)(Aptr + 4);
        unsigned hi, lo;
        split2(f0.x, f0.y, hi, lo);
        As[0][ast_base + (0 ^ xa)] = hi; As[0][PLANE + ast_base + (0 ^ xa)] = lo;
        split2(f0.z, f0.w, hi, lo);
        As[0][ast_base + (1 ^ xa)] = hi; As[0][PLANE + ast_base + (1 ^ xa)] = lo;
        split2(f1.x, f1.y, hi, lo);
        As[0][ast_base + (2 ^ xa)] = hi; As[0][PLANE + ast_base + (2 ^ xa)] = lo;
        split2(f1.z, f1.w, hi, lo);
        As[0][ast_base + (3 ^ xa)] = hi; As[0][PLANE + ast_base + (3 ^ xa)] = lo;
#pragma unroll
        for (int i = 0; i < 4; i++) {
            int k = 8 * bh2 + 2 * i;
            float b0 = (gcol < N) ? B[(size_t)k * N + gcol] : 0.f;
            float b1 = (gcol < N) ? B[(size_t)(k + 1) * N + gcol] : 0.f;
            split2(b0, b1, hi, lo);
            Bs[0][bst_base + (i ^ xb)] = hi;
            Bs[0][PLANE + bst_base + (i ^ xb)] = lo;
        }
    }
    __syncthreads();

    int iters = K / TBK;
    for (int it = 1; it <= iters; it++) {
        bool has = (it < iters);
        float4 f0, f1;
        float bg[8];
        if (has) {
            int k0 = it * TBK;
            f0 = *(const float4*)(Aptr + k0);
            f1 = *(const float4*)(Aptr + k0 + 4);
#pragma unroll
            for (int i = 0; i < 4; i++) {
                int k = k0 + 8 * bh2 + 2 * i;
                bg[2 * i]     = (gcol < N) ? B[(size_t)k * N + gcol] : 0.f;
                bg[2 * i + 1] = (gcol < N) ? B[(size_t)(k + 1) * N + gcol] : 0.f;
            }
        }
        {
            const unsigned* Ab = As[(it - 1) & 1];
            const unsigned* Bb = Bs[(it - 1) & 1];
            unsigned ahf[2][4], alf[2][4];
#pragma unroll
            for (int i = 0; i < 2; i++) {
                ahf[i][0] = Ab[idxA[i][0]];
                ahf[i][1] = Ab[idxA[i][1]];
                ahf[i][2] = Ab[idxA[i][0] + 4];
                ahf[i][3] = Ab[idxA[i][1] + 4];
                alf[i][0] = Ab[PLANE + idxA[i][0]];
                alf[i][1] = Ab[PLANE + idxA[i][1]];
                alf[i][2] = Ab[PLANE + idxA[i][0] + 4];
                alf[i][3] = Ab[PLANE + idxA[i][1] + 4];
            }
#pragma unroll
            for (int j = 0; j < 8; j++) {
                unsigned bh0 = Bb[idxB[j]];
                unsigned bh1 = Bb[idxB[j] + 4];
                unsigned bl0 = Bb[PLANE + idxB[j]];
                unsigned bl1 = Bb[PLANE + idxB[j] + 4];
                mma_bf16(acc[0][j], ahf[0], bh0, bh1);
                mma_bf16(acc[1][j], ahf[1], bh0, bh1);
                mma_bf16(acc[0][j], ahf[0], bl0, bl1);
                mma_bf16(acc[1][j], ahf[1], bl0, bl1);
                mma_bf16(acc[0][j], alf[0], bh0, bh1);
                mma_bf16(acc[1][j], alf[1], bh0, bh1);
            }
        }
        if (has) {
            int buf = it & 1;
            unsigned hi, lo;
            split2(f0.x, f0.y, hi, lo);
            As[buf][ast_base + (0 ^ xa)] = hi; As[buf][PLANE + ast_base + (0 ^ xa)] = lo;
            split2(f0.z, f0.w, hi, lo);
            As[buf][ast_base + (1 ^ xa)] = hi; As[buf][PLANE + ast_base + (1 ^ xa)] = lo;
            split2(f1.x, f1.y, hi, lo);
            As[buf][ast_base + (2 ^ xa)] = hi; As[buf][PLANE + ast_base + (2 ^ xa)] = lo;
            split2(f1.z, f1.w, hi, lo);
            As[buf][ast_base + (3 ^ xa)] = hi; As[buf][PLANE + ast_base + (3 ^ xa)] = lo;
#pragma unroll
            for (int i = 0; i < 4; i++) {
                split2(bg[2 * i], bg[2 * i + 1], hi, lo);
                Bs[buf][bst_base + (i ^ xb)] = hi;
                Bs[buf][PLANE + bst_base + (i ^ xb)] = lo;
            }
        }
        __syncthreads();
    }

#pragma unroll
    for (int i = 0; i < 2; i++) {
        int row = bm + wm * 32 + i * 16 + fg;
#pragma unroll
        for (int j = 0; j < 8; j++) {
            int col = bn + wn * 64 + j * 8 + ft * 2;
            if (col < N) {
                float b0 = bias[col], b1 = bias[col + 1];
                float v0 = acc[i][j][0] + b0;
                float v1 = acc[i][j][1] + b1;
                float v2 = acc[i][j][2] + b0;
                float v3 = acc[i][j][3] + b1;
                if (act == 1) {
                    v0 = v0 / (1.f + __expf(-v0));
                    v1 = v1 / (1.f + __expf(-v1));
                    v2 = v2 / (1.f + __expf(-v2));
                    v3 = v3 / (1.f + __expf(-v3));
                }
                *(float2*)&C[(size_t)row * N + col] = make_float2(v0, v1);
                *(float2*)&C[(size_t)(row + 8) * N + col] = make_float2(v2, v3);
            }
        }
    }
}

// ===========================================================================
// Scan v5: 2-step micro-WY (R11 algebra) with 4-way row split.
// 256 blocks: blockIdx.x = bh*4 + quarter; each block owns 16 rows of M.
// 128 threads: rr = tid>>3 (row in quarter), g = tid&7 (8 cols each).
// 2 blocks/SM resident -> 2 warps/SMSP; ~40% fewer instr/warp/step.
// ===========================================================================
#define SDEPTH 8
#define SBUF 224

__global__ __launch_bounds__(128) void scan_kernel(
    const float* __restrict__ base,    // [B,S,H,3,HD]
    const float* __restrict__ ctrl,    // [B,S,H,5]
    const float* __restrict__ memory0, // [B,H,HD,HD]
    float* __restrict__ ys,            // [B,S,D]
    float* __restrict__ mfinal)        // [B,H,HD,HD]
{
    __shared__ __align__(16) float sbuf[SDEPTH][SBUF];

    int bh      = blockIdx.x >> 2;
    int quarter = blockIdx.x & 3;
    int b = bh >> 4, h = bh & 15;
    int tid = threadIdx.x;
    int rr = tid >> 3;                 // 0..15
    int r  = quarter * 16 + rr;        // global row 0..63
    int g  = tid & 7;                  // column group (8 cols)

    float m[8];
    {
        const float* M0 = memory0 + (((size_t)bh * HDIM + r) * HDIM + g * 8);
#pragma unroll
        for (int jj = 0; jj < 8; jj++) m[jj] = M0[jj];
    }

    const float* bsrc = base + ((size_t)b * SS * HH + h) * 192;
    const float* csrc = ctrl + (size_t)b * SS * 80 + h * 5;
    float* yptr = ys + (size_t)b * SS * DD + h * HDIM + r;

    unsigned sb_addr[SDEPTH];
#pragma unroll
    for (int d = 0; d < SDEPTH; d++)
        sb_addr[d] = (unsigned)__cvta_generic_to_shared(&sbuf[d][0]);

#define SCAN_ISSUE(st) do {                                              \
        unsigned sa_ = sb_addr[(st) & (SDEPTH - 1)];                     \
        if (tid < 48)                                                    \
            cpa16(sa_ + tid * 16, bsrc + (size_t)(st) * 3072 + tid * 4); \
        else if (tid < 53)                                               \
            cpa4(sa_ + 768 + (tid - 48) * 4,                             \
                 csrc + (size_t)(st) * 80 + (tid - 48));                 \
        cpcommit();                                                      \
    } while (0)

    // prologue: stages 0..5 (6 groups)
#pragma unroll
    for (int p = 0; p < 6; p++) SCAN_ISSUE(p);

    for (int s = 0; s < SS; s += 2) {
        if (s + 6 < SS) SCAN_ISSUE(s + 6); else cpcommit();
        if (s + 7 < SS) SCAN_ISSUE(s + 7); else cpcommit();
        cpwait<6>();         // stages s and s+1 complete
        __syncthreads();

        const float* s1 = sbuf[s & (SDEPTH - 1)];
        const float* s2 = sbuf[(s + 1) & (SDEPTH - 1)];

        float c0a = s1[192], c1a = s1[193], c2a = s1[194];
        float c0b = s2[192], c1b = s2[193], c2b = s2[194];
        float n1 = 1.f / (1.f + __expf(-s1[195]));
        float a1 = 1.f / (1.f + __expf(-s1[196]));
        float n2 = 1.f / (1.f + __expf(-s2[195]));
        float a2 = 1.f / (1.f + __expf(-s2[196]));
        float v1 = s1[64 + r], v2 = s2[64 + r];

        float kr1[8], qr1[8], kr2[8], qr2[8];
#pragma unroll
        for (int w = 0; w < 2; w++) {
            *(float4*)&kr1[w * 4] = *(const float4*)&s1[g * 8 + w * 4];
            *(float4*)&qr1[w * 4] = *(const float4*)&s1[128 + g * 8 + w * 4];
            *(float4*)&kr2[w * 4] = *(const float4*)&s2[g * 8 + w * 4];
            *(float4*)&qr2[w * 4] = *(const float4*)&s2[128 + g * 8 + w * 4];
        }

        // 6 partial sums over this thread's 8 columns (2-way split each)
        float dk1a = 0.f, dk1b = 0.f, dq1a = 0.f, dq1b = 0.f;
        float dk2a = 0.f, dk2b = 0.f, dq2a = 0.f, dq2b = 0.f;
        float gka = 0.f, gkb = 0.f, gqa = 0.f, gqb = 0.f;
#pragma unroll
        for (int jj = 0; jj < 8; jj += 2) {
            dk1a += m[jj] * kr1[jj];       dk1b += m[jj + 1] * kr1[jj + 1];
            dq1a += m[jj] * qr1[jj];       dq1b += m[jj + 1] * qr1[jj + 1];
            dk2a += m[jj] * kr2[jj];       dk2b += m[jj + 1] * kr2[jj + 1];
            dq2a += m[jj] * qr2[jj];       dq2b += m[jj + 1] * qr2[jj + 1];
            gka  += kr1[jj] * kr2[jj];     gkb  += kr1[jj + 1] * kr2[jj + 1];
            gqa  += kr1[jj] * qr2[jj];     gqb  += kr1[jj + 1] * qr2[jj + 1];
        }
        float dk1 = dk1a + dk1b, dq1 = dq1a + dq1b;
        float dk2 = dk2a + dk2b, dq2 = dq2a + dq2b;
        float gk  = gka + gkb,   gq  = gqa + gqb;

        // one reduction wave across the 8-lane row group: xor 1, 2, 4
#pragma unroll
        for (int d = 1; d <= 4; d <<= 1) {
            dk1 += __shfl_xor_sync(0xffffffffu, dk1, d);
            dq1 += __shfl_xor_sync(0xffffffffu, dq1, d);
            dk2 += __shfl_xor_sync(0xffffffffu, dk2, d);
            dq2 += __shfl_xor_sync(0xffffffffu, dq2, d);
            gk  += __shfl_xor_sync(0xffffffffu, gk, d);
            gq  += __shfl_xor_sync(0xffffffffu, gq, d);
        }

        // substitution (scalar per row)
        float e1 = n1 * (c0a * dk1 - c1a * v1);
        float y1 = c2a * dq1;
        float gkk = c0a * c0b * gk;
        float gkq = c0a * c2b * gq;
        float e2 = n2 * (a1 * c0b * dk2 + e1 * gkk - c1b * v2);
        float y2 = a1 * c2b * dq2 + e1 * gkq;

        if (g == 0) {
            yptr[(size_t)s * DD] = y1;
            yptr[(size_t)(s + 1) * DD] = y2;
        }

        // fused update
        float a12 = a1 * a2;
        float w1 = a2 * e1 * c0a;
        float w2 = e2 * c0b;
#pragma unroll
        for (int jj = 0; jj < 8; jj++)
            m[jj] = a12 * m[jj] + w1 * kr1[jj] + w2 * kr2[jj];

        __syncthreads();   // reads of stages s, s+1 done before slot reuse
    }

    float* MF = mfinal + (((size_t)bh * HDIM + r) * HDIM + g * 8);
#pragma unroll
    for (int jj = 0; jj < 8; jj++) MF[jj] = m[jj];
}

// ===========================================================================
extern "C" void kernel_launch(void* const* d_in, const int* in_sizes, int n_in,
                              void* d_out, int out_size)
{
    (void)in_sizes; (void)n_in;
    const float* x       = (const float*)d_in[0];
    const float* memory0 = (const float*)d_in[1];
    const float* W_in    = (const float*)d_in[2];
    const float* b_in    = (const float*)d_in[3];
    const float* Wc1     = (const float*)d_in[4];
    const float* bc1     = (const float*)d_in[5];
    const float* Wc2     = (const float*)d_in[6];
    const float* bc2     = (const float*)d_in[7];
    const float* W_out   = (const float*)d_in[8];
    const float* b_out   = (const float*)d_in[9];

    float* out = (float*)d_out;

    float *base, *hidden, *ctrl, *ys, *mf_scratch;
    cudaGetSymbolAddress((void**)&base,       g_base);
    cudaGetSymbolAddress((void**)&hidden,     g_hidden);
    cudaGetSymbolAddress((void**)&ctrl,       g_ctrl);
    cudaGetSymbolAddress((void**)&ys,         g_ys);
    cudaGetSymbolAddress((void**)&mf_scratch, g_mf);

    const size_t OUT_ELEMS = (size_t)MR * DD;
    const size_t MF_ELEMS  = (size_t)BB * HH * HDIM * HDIM;
    float* mfinal = ((size_t)out_size >= OUT_ELEMS + MF_ELEMS)
                        ? (out + OUT_ELEMS) : mf_scratch;

    // ---- fork: ctrl path (gemm2 -> gemm3) on s2, base gemm on main ----
    cudaEventRecord(g_hx.e1, 0);
    cudaStreamWaitEvent(g_hx.s2, g_hx.e1, 0);

    gemm_bf16x3<<<dim3(DD / 128, MR / TBM), 256, 0, g_hx.s2>>>(
        x, Wc1, bc1, hidden, MR, DD, DD, 1);
    gemm_bf16x3<<<dim3(1, MR / TBM), 256, 0, g_hx.s2>>>(
        hidden, Wc2, bc2, ctrl, MR, 5 * HH, DD, 0);
    cudaEventRecord(g_hx.e2, g_hx.s2);

    gemm_bf16x3<<<dim3(3 * DD / 128, MR / TBM), 256>>>(
        x, W_in, b_in, base, MR, 3 * DD, DD, 0);

    // ---- join: scan needs base (main) + ctrl (s2) ----
    cudaStreamWaitEvent((cudaStream_t)0, g_hx.e2, 0);

    // sequential scan (2-step chunked, 4-way row split)
    scan_kernel<<<BB * HH * 4, 128>>>(base, ctrl, memory0, ys, mfinal);
    // out = ys @ W_out + b_out
    gemm_bf16x3<<<dim3(DD / 128, MR / TBM), 256>>>(
        ys, W_out, b_out, out, MR, DD, DD, 0);
}

// round 14
// speedup vs baseline: 1.4536x; 1.0426x over previous
#include <cuda_runtime.h>
#include <cuda_bf16.h>
#include <math.h>
#include <stdint.h>

#define BB 4
#define SS 2048
#define DD 1024
#define HH 16
#define HDIM 64
#define MR (BB * SS)   // 8192

// ---- scratch (device globals: allocation-free per harness rules) ----
__device__ float g_base[(size_t)MR * 3 * DD];      // [8192,3072]
__device__ float g_hidden[(size_t)MR * DD];        // [8192,1024]
__device__ float g_ctrl[(size_t)MR * 80 + 16];     // [8192,80] (+pad)
__device__ float g_ys[(size_t)MR * DD];            // [8192,1024]
__device__ float g_mf[(size_t)BB * HH * HDIM * HDIM];

// ---- second stream + fork/join events (module-load construction; outside
// graph capture, no device allocation) ----
struct HxStreams {
    cudaStream_t s2;
    cudaEvent_t e1, e2;
    HxStreams() {
        cudaStreamCreateWithFlags(&s2, cudaStreamNonBlocking);
        cudaEventCreateWithFlags(&e1, cudaEventDisableTiming);
        cudaEventCreateWithFlags(&e2, cudaEventDisableTiming);
    }
};
static HxStreams g_hx;

// ===========================================================================
// helpers
// ===========================================================================
__device__ __forceinline__ void split2(float a0, float a1,
                                       unsigned& hi, unsigned& lo) {
    asm("cvt.rn.bf16x2.f32 %0, %1, %2;" : "=r"(hi) : "f"(a1), "f"(a0));
    float h0 = __uint_as_float(hi << 16);
    float h1 = __uint_as_float(hi & 0xffff0000u);
    float r0 = a0 - h0, r1 = a1 - h1;
    asm("cvt.rn.bf16x2.f32 %0, %1, %2;" : "=r"(lo) : "f"(r1), "f"(r0));
}

__device__ __forceinline__ void mma_bf16(float* c, const unsigned* a,
                                         unsigned b0, unsigned b1) {
    asm volatile(
        "mma.sync.aligned.m16n8k16.row.col.f32.bf16.bf16.f32 "
        "{%0,%1,%2,%3}, {%4,%5,%6,%7}, {%8,%9}, {%0,%1,%2,%3};"
        : "+f"(c[0]), "+f"(c[1]), "+f"(c[2]), "+f"(c[3])
        : "r"(a[0]), "r"(a[1]), "r"(a[2]), "r"(a[3]), "r"(b0), "r"(b1));
}

__device__ __forceinline__ void cpa16(uint32_t s, const void* g) {
    asm volatile("cp.async.ca.shared.global [%0], [%1], 16;"
                 :: "r"(s), "l"(g) : "memory");
}
__device__ __forceinline__ void cpa4(uint32_t s, const void* g) {
    asm volatile("cp.async.ca.shared.global [%0], [%1], 4;"
                 :: "r"(s), "l"(g) : "memory");
}
__device__ __forceinline__ void cpcommit() {
    asm volatile("cp.async.commit_group;" ::: "memory");
}
template <int N>
__device__ __forceinline__ void cpwait() {
    asm volatile("cp.async.wait_group %0;" :: "n"(N) : "memory");
}

// ===========================================================================
// Legacy bf16x3 GEMM (R5..R13-exact)
// ===========================================================================
#define TBM 128
#define TBK 16
#define XSTR 12
#define PLANE (TBM * XSTR)

__global__ __launch_bounds__(256) void gemm_bf16x3(
    const float* __restrict__ A, const float* __restrict__ B,
    const float* __restrict__ bias, float* __restrict__ C,
    int M, int N, int K, int act)
{
    __shared__ __align__(16) unsigned As[2][2 * PLANE];
    __shared__ __align__(16) unsigned Bs[2][2 * PLANE];

    int tid  = threadIdx.x;
    int lane = tid & 31;
    int warp = tid >> 5;
    int wm = warp >> 1, wn = warp & 1;
    int bm = blockIdx.y * TBM;
    int bn = blockIdx.x * 128;

    int arow = tid >> 1, ah = tid & 1;
    const float* Aptr = A + (size_t)(bm + arow) * K + ah * 8;
    int xa = (arow & 3) ^ ((arow >> 3) & 3);
    int ast_base = arow * XSTR + 4 * ah;
    int bnn = tid & 127, bh2 = tid >> 7;
    int gcol = bn + bnn;
    int xb = (bnn & 3) ^ ((bnn >> 3) & 3);
    int bst_base = bnn * XSTR + 4 * bh2;

    int fg = lane >> 2, ft = lane & 3;
    int idxA[2][2];
#pragma unroll
    for (int i = 0; i < 2; i++)
#pragma unroll
        for (int d = 0; d < 2; d++) {
            int row = wm * 32 + i * 16 + d * 8 + fg;
            idxA[i][d] = row * XSTR + (ft ^ (row & 3) ^ ((row >> 3) & 3));
        }
    int idxB[8];
#pragma unroll
    for (int j = 0; j < 8; j++) {
        int n = wn * 64 + j * 8 + fg;
        idxB[j] = n * XSTR + (ft ^ (n & 3) ^ ((n >> 3) & 3));
    }

    float acc[2][8][4];
#pragma unroll
    for (int i = 0; i < 2; i++)
#pragma unroll
        for (int j = 0; j < 8; j++)
#pragma unroll
            for (int l = 0; l < 4; l++) acc[i][j][l] = 0.f;

    {
        float4 f0 = *(const float4*)Aptr;
        float4 f1 = *(const float4*)(Aptr + 4);
        unsigned hi, lo;
        split2(f0.x, f0.y, hi, lo);
        As[0][ast_base + (0 ^ xa)] = hi; As[0][PLANE + ast_base + (0 ^ xa)] = lo;
        split2(f0.z, f0.w, hi, lo);
        As[0][ast_base + (1 ^ xa)] = hi; As[0][PLANE + ast_base + (1 ^ xa)] = lo;
        split2(f1.x, f1.y, hi, lo);
        As[0][ast_base + (2 ^ xa)] = hi; As[0][PLANE + ast_base + (2 ^ xa)] = lo;
        split2(f1.z, f1.w, hi, lo);
        As[0][ast_base + (3 ^ xa)] = hi; As[0][PLANE + ast_base + (3 ^ xa)] = lo;
#pragma unroll
        for (int i = 0; i < 4; i++) {
            int k = 8 * bh2 + 2 * i;
            float b0 = (gcol < N) ? B[(size_t)k * N + gcol] : 0.f;
            float b1 = (gcol < N) ? B[(size_t)(k + 1) * N + gcol] : 0.f;
            split2(b0, b1, hi, lo);
            Bs[0][bst_base + (i ^ xb)] = hi;
            Bs[0][PLANE + bst_base + (i ^ xb)] = lo;
        }
    }
    __syncthreads();

    int iters = K / TBK;
    for (int it = 1; it <= iters; it++) {
        bool has = (it < iters);
        float4 f0, f1;
        float bg[8];
        if (has) {
            int k0 = it * TBK;
            f0 = *(const float4*)(Aptr + k0);
            f1 = *(const float4*)(Aptr + k0 + 4);
#pragma unroll
            for (int i = 0; i < 4; i++) {
                int k = k0 + 8 * bh2 + 2 * i;
                bg[2 * i]     = (gcol < N) ? B[(size_t)k * N + gcol] : 0.f;
                bg[2 * i + 1] = (gcol < N) ? B[(size_t)(k + 1) * N + gcol] : 0.f;
            }
        }
        {
            const unsigned* Ab = As[(it - 1) & 1];
            const unsigned* Bb = Bs[(it - 1) & 1];
            unsigned ahf[2][4], alf[2][4];
#pragma unroll
            for (int i = 0; i < 2; i++) {
                ahf[i][0] = Ab[idxA[i][0]];
                ahf[i][1] = Ab[idxA[i][1]];
                ahf[i][2] = Ab[idxA[i][0] + 4];
                ahf[i][3] = Ab[idxA[i][1] + 4];
                alf[i][0] = Ab[PLANE + idxA[i][0]];
                alf[i][1] = Ab[PLANE + idxA[i][1]];
                alf[i][2] = Ab[PLANE + idxA[i][0] + 4];
                alf[i][3] = Ab[PLANE + idxA[i][1] + 4];
            }
#pragma unroll
            for (int j = 0; j < 8; j++) {
                unsigned bh0 = Bb[idxB[j]];
                unsigned bh1 = Bb[idxB[j] + 4];
                unsigned bl0 = Bb[PLANE + idxB[j]];
                unsigned bl1 = Bb[PLANE + idxB[j] + 4];
                mma_bf16(acc[0][j], ahf[0], bh0, bh1);
                mma_bf16(acc[1][j], ahf[1], bh0, bh1);
                mma_bf16(acc[0][j], ahf[0], bl0, bl1);
                mma_bf16(acc[1][j], ahf[1], bl0, bl1);
                mma_bf16(acc[0][j], alf[0], bh0, bh1);
                mma_bf16(acc[1][j], alf[1], bh0, bh1);
            }
        }
        if (has) {
            int buf = it & 1;
            unsigned hi, lo;
            split2(f0.x, f0.y, hi, lo);
            As[buf][ast_base + (0 ^ xa)] = hi; As[buf][PLANE + ast_base + (0 ^ xa)] = lo;
            split2(f0.z, f0.w, hi, lo);
            As[buf][ast_base + (1 ^ xa)] = hi; As[buf][PLANE + ast_base + (1 ^ xa)] = lo;
            split2(f1.x, f1.y, hi, lo);
            As[buf][ast_base + (2 ^ xa)] = hi; As[buf][PLANE + ast_base + (2 ^ xa)] = lo;
            split2(f1.z, f1.w, hi, lo);
            As[buf][ast_base + (3 ^ xa)] = hi; As[buf][PLANE + ast_base + (3 ^ xa)] = lo;
#pragma unroll
            for (int i = 0; i < 4; i++) {
                split2(bg[2 * i], bg[2 * i + 1], hi, lo);
                Bs[buf][bst_base + (i ^ xb)] = hi;
                Bs[buf][PLANE + bst_base + (i ^ xb)] = lo;
            }
        }
        __syncthreads();
    }

#pragma unroll
    for (int i = 0; i < 2; i++) {
        int row = bm + wm * 32 + i * 16 + fg;
#pragma unroll
        for (int j = 0; j < 8; j++) {
            int col = bn + wn * 64 + j * 8 + ft * 2;
            if (col < N) {
                float b0 = bias[col], b1 = bias[col + 1];
                float v0 = acc[i][j][0] + b0;
                float v1 = acc[i][j][1] + b1;
                float v2 = acc[i][j][2] + b0;
                float v3 = acc[i][j][3] + b1;
                if (act == 1) {
                    v0 = v0 / (1.f + __expf(-v0));
                    v1 = v1 / (1.f + __expf(-v1));
                    v2 = v2 / (1.f + __expf(-v2));
                    v3 = v3 / (1.f + __expf(-v3));
                }
                *(float2*)&C[(size_t)row * N + col] = make_float2(v0, v1);
                *(float2*)&C[(size_t)(row + 8) * N + col] = make_float2(v2, v3);
            }
        }
    }
}

// ===========================================================================
// Scan v6: 2-step micro-WY with 8-way row split.
// 512 blocks: blockIdx.x = bh*8 + oct; each block owns 8 rows of M.
// 128 threads: rr = tid>>4 (row in oct), g = tid&15 (4 cols each).
// ~3.5 blocks/SM resident; ~40% fewer instr/warp vs v5.
// ===========================================================================
#define SDEPTH 8
#define SBUF 224

__global__ __launch_bounds__(128) void scan_kernel(
    const float* __restrict__ base,    // [B,S,H,3,HD]
    const float* __restrict__ ctrl,    // [B,S,H,5]
    const float* __restrict__ memory0, // [B,H,HD,HD]
    float* __restrict__ ys,            // [B,S,D]
    float* __restrict__ mfinal)        // [B,H,HD,HD]
{
    __shared__ __align__(16) float sbuf[SDEPTH][SBUF];

    int bh  = blockIdx.x >> 3;
    int oct = blockIdx.x & 7;
    int b = bh >> 4, h = bh & 15;
    int tid = threadIdx.x;
    int rr = tid >> 4;                 // 0..7
    int r  = oct * 8 + rr;             // global row 0..63
    int g  = tid & 15;                 // column group (4 cols)

    float m[4];
    {
        const float* M0 = memory0 + (((size_t)bh * HDIM + r) * HDIM + g * 4);
#pragma unroll
        for (int jj = 0; jj < 4; jj++) m[jj] = M0[jj];
    }

    const float* bsrc = base + ((size_t)b * SS * HH + h) * 192;
    const float* csrc = ctrl + (size_t)b * SS * 80 + h * 5;
    float* yptr = ys + (size_t)b * SS * DD + h * HDIM + r;

    unsigned sb_addr[SDEPTH];
#pragma unroll
    for (int d = 0; d < SDEPTH; d++)
        sb_addr[d] = (unsigned)__cvta_generic_to_shared(&sbuf[d][0]);

#define SCAN_ISSUE(st) do {                                              \
        unsigned sa_ = sb_addr[(st) & (SDEPTH - 1)];                     \
        if (tid < 48)                                                    \
            cpa16(sa_ + tid * 16, bsrc + (size_t)(st) * 3072 + tid * 4); \
        else if (tid < 53)                                               \
            cpa4(sa_ + 768 + (tid - 48) * 4,                             \
                 csrc + (size_t)(st) * 80 + (tid - 48));                 \
        cpcommit();                                                      \
    } while (0)

    // prologue: stages 0..5 (6 groups)
#pragma unroll
    for (int p = 0; p < 6; p++) SCAN_ISSUE(p);

    for (int s = 0; s < SS; s += 2) {
        if (s + 6 < SS) SCAN_ISSUE(s + 6); else cpcommit();
        if (s + 7 < SS) SCAN_ISSUE(s + 7); else cpcommit();
        cpwait<6>();         // stages s and s+1 complete
        __syncthreads();

        const float* s1 = sbuf[s & (SDEPTH - 1)];
        const float* s2 = sbuf[(s + 1) & (SDEPTH - 1)];

        float c0a = s1[192], c1a = s1[193], c2a = s1[194];
        float c0b = s2[192], c1b = s2[193], c2b = s2[194];
        float n1 = 1.f / (1.f + __expf(-s1[195]));
        float a1 = 1.f / (1.f + __expf(-s1[196]));
        float n2 = 1.f / (1.f + __expf(-s2[195]));
        float a2 = 1.f / (1.f + __expf(-s2[196]));
        float v1 = s1[64 + r], v2 = s2[64 + r];

        float4 kr1 = *(const float4*)&s1[g * 4];
        float4 qr1 = *(const float4*)&s1[128 + g * 4];
        float4 kr2 = *(const float4*)&s2[g * 4];
        float4 qr2 = *(const float4*)&s2[128 + g * 4];

        // 6 partial sums over this thread's 4 columns
        float dk1 = m[0]*kr1.x + m[1]*kr1.y + m[2]*kr1.z + m[3]*kr1.w;
        float dq1 = m[0]*qr1.x + m[1]*qr1.y + m[2]*qr1.z + m[3]*qr1.w;
        float dk2 = m[0]*kr2.x + m[1]*kr2.y + m[2]*kr2.z + m[3]*kr2.w;
        float dq2 = m[0]*qr2.x + m[1]*qr2.y + m[2]*qr2.z + m[3]*qr2.w;
        float gk  = kr1.x*kr2.x + kr1.y*kr2.y + kr1.z*kr2.z + kr1.w*kr2.w;
        float gq  = kr1.x*qr2.x + kr1.y*qr2.y + kr1.z*qr2.z + kr1.w*qr2.w;

        // reduction across the 16-lane row group: xor 1, 2, 4, 8
#pragma unroll
        for (int d = 1; d <= 8; d <<= 1) {
            dk1 += __shfl_xor_sync(0xffffffffu, dk1, d);
            dq1 += __shfl_xor_sync(0xffffffffu, dq1, d);
            dk2 += __shfl_xor_sync(0xffffffffu, dk2, d);
            dq2 += __shfl_xor_sync(0xffffffffu, dq2, d);
            gk  += __shfl_xor_sync(0xffffffffu, gk, d);
            gq  += __shfl_xor_sync(0xffffffffu, gq, d);
        }

        // substitution (scalar per row)
        float e1 = n1 * (c0a * dk1 - c1a * v1);
        float y1 = c2a * dq1;
        float gkk = c0a * c0b * gk;
        float gkq = c0a * c2b * gq;
        float e2 = n2 * (a1 * c0b * dk2 + e1 * gkk - c1b * v2);
        float y2 = a1 * c2b * dq2 + e1 * gkq;

        if (g == 0) {
            yptr[(size_t)s * DD] = y1;
            yptr[(size_t)(s + 1) * DD] = y2;
        }

        // fused update
        float a12 = a1 * a2;
        float w1 = a2 * e1 * c0a;
        float w2 = e2 * c0b;
        m[0] = a12 * m[0] + w1 * kr1.x + w2 * kr2.x;
        m[1] = a12 * m[1] + w1 * kr1.y + w2 * kr2.y;
        m[2] = a12 * m[2] + w1 * kr1.z + w2 * kr2.z;
        m[3] = a12 * m[3] + w1 * kr1.w + w2 * kr2.w;

        __syncthreads();   // reads of stages s, s+1 done before slot reuse
    }

    float* MF = mfinal + (((size_t)bh * HDIM + r) * HDIM + g * 4);
#pragma unroll
    for (int jj = 0; jj < 4; jj++) MF[jj] = m[jj];
}

// ===========================================================================
extern "C" void kernel_launch(void* const* d_in, const int* in_sizes, int n_in,
                              void* d_out, int out_size)
{
    (void)in_sizes; (void)n_in;
    const float* x       = (const float*)d_in[0];
    const float* memory0 = (const float*)d_in[1];
    const float* W_in    = (const float*)d_in[2];
    const float* b_in    = (const float*)d_in[3];
    const float* Wc1     = (const float*)d_in[4];
    const float* bc1     = (const float*)d_in[5];
    const float* Wc2     = (const float*)d_in[6];
    const float* bc2     = (const float*)d_in[7];
    const float* W_out   = (const float*)d_in[8];
    const float* b_out   = (const float*)d_in[9];

    float* out = (float*)d_out;

    float *base, *hidden, *ctrl, *ys, *mf_scratch;
    cudaGetSymbolAddress((void**)&base,       g_base);
    cudaGetSymbolAddress((void**)&hidden,     g_hidden);
    cudaGetSymbolAddress((void**)&ctrl,       g_ctrl);
    cudaGetSymbolAddress((void**)&ys,         g_ys);
    cudaGetSymbolAddress((void**)&mf_scratch, g_mf);

    const size_t OUT_ELEMS = (size_t)MR * DD;
    const size_t MF_ELEMS  = (size_t)BB * HH * HDIM * HDIM;
    float* mfinal = ((size_t)out_size >= OUT_ELEMS + MF_ELEMS)
                        ? (out + OUT_ELEMS) : mf_scratch;

    // ---- fork: ctrl path (gemm2 -> gemm3) on s2, base gemm on main ----
    cudaEventRecord(g_hx.e1, 0);
    cudaStreamWaitEvent(g_hx.s2, g_hx.e1, 0);

    gemm_bf16x3<<<dim3(DD / 128, MR / TBM), 256, 0, g_hx.s2>>>(
        x, Wc1, bc1, hidden, MR, DD, DD, 1);
    gemm_bf16x3<<<dim3(1, MR / TBM), 256, 0, g_hx.s2>>>(
        hidden, Wc2, bc2, ctrl, MR, 5 * HH, DD, 0);
    cudaEventRecord(g_hx.e2, g_hx.s2);

    gemm_bf16x3<<<dim3(3 * DD / 128, MR / TBM), 256>>>(
        x, W_in, b_in, base, MR, 3 * DD, DD, 0);

    // ---- join: scan needs base (main) + ctrl (s2) ----
    cudaStreamWaitEvent((cudaStream_t)0, g_hx.e2, 0);

    // sequential scan (2-step chunked, 8-way row split)
    scan_kernel<<<BB * HH * 8, 128>>>(base, ctrl, memory0, ys, mfinal);
    // out = ys @ W_out + b_out
    gemm_bf16x3<<<dim3(DD / 128, MR / TBM), 256>>>(
        ys, W_out, b_out, out, MR, DD, DD, 0);
}

// round 15
// speedup vs baseline: 1.5205x; 1.0461x over previous
#include <cuda_runtime.h>
#include <cuda_bf16.h>
#include <math.h>
#include <stdint.h>

#define BB 4
#define SS 2048
#define DD 1024
#define HH 16
#define HDIM 64
#define MR (BB * SS)   // 8192

// ---- scratch (device globals: allocation-free per harness rules) ----
__device__ float g_base[(size_t)MR * 3 * DD];      // [8192,3072]
__device__ float g_hidden[(size_t)MR * DD];        // [8192,1024]
__device__ float g_ctrl[(size_t)MR * 80 + 16];     // [8192,80] (+pad)
__device__ float g_ys[(size_t)MR * DD];            // [8192,1024]
__device__ float g_mf[(size_t)BB * HH * HDIM * HDIM];

// ---- second stream + fork/join events (module-load construction; outside
// graph capture, no device allocation) ----
struct HxStreams {
    cudaStream_t s2;
    cudaEvent_t e1, e2;
    HxStreams() {
        cudaStreamCreateWithFlags(&s2, cudaStreamNonBlocking);
        cudaEventCreateWithFlags(&e1, cudaEventDisableTiming);
        cudaEventCreateWithFlags(&e2, cudaEventDisableTiming);
    }
};
static HxStreams g_hx;

// ===========================================================================
// helpers
// ===========================================================================
__device__ __forceinline__ void split2(float a0, float a1,
                                       unsigned& hi, unsigned& lo) {
    asm("cvt.rn.bf16x2.f32 %0, %1, %2;" : "=r"(hi) : "f"(a1), "f"(a0));
    float h0 = __uint_as_float(hi << 16);
    float h1 = __uint_as_float(hi & 0xffff0000u);
    float r0 = a0 - h0, r1 = a1 - h1;
    asm("cvt.rn.bf16x2.f32 %0, %1, %2;" : "=r"(lo) : "f"(r1), "f"(r0));
}

__device__ __forceinline__ void mma_bf16(float* c, const unsigned* a,
                                         unsigned b0, unsigned b1) {
    asm volatile(
        "mma.sync.aligned.m16n8k16.row.col.f32.bf16.bf16.f32 "
        "{%0,%1,%2,%3}, {%4,%5,%6,%7}, {%8,%9}, {%0,%1,%2,%3};"
        : "+f"(c[0]), "+f"(c[1]), "+f"(c[2]), "+f"(c[3])
        : "r"(a[0]), "r"(a[1]), "r"(a[2]), "r"(a[3]), "r"(b0), "r"(b1));
}

__device__ __forceinline__ void cpa16(uint32_t s, const void* g) {
    asm volatile("cp.async.ca.shared.global [%0], [%1], 16;"
                 :: "r"(s), "l"(g) : "memory");
}
__device__ __forceinline__ void cpa4(uint32_t s, const void* g) {
    asm volatile("cp.async.ca.shared.global [%0], [%1], 4;"
                 :: "r"(s), "l"(g) : "memory");
}
__device__ __forceinline__ void cpcommit() {
    asm volatile("cp.async.commit_group;" ::: "memory");
}
template <int N>
__device__ __forceinline__ void cpwait() {
    asm volatile("cp.async.wait_group %0;" :: "n"(N) : "memory");
}

// ===========================================================================
// Legacy bf16x3 GEMM (R5..R14-exact)
// ===========================================================================
#define TBM 128
#define TBK 16
#define XSTR 12
#define PLANE (TBM * XSTR)

__global__ __launch_bounds__(256) void gemm_bf16x3(
    const float* __restrict__ A, const float* __restrict__ B,
    const float* __restrict__ bias, float* __restrict__ C,
    int M, int N, int K, int act)
{
    __shared__ __align__(16) unsigned As[2][2 * PLANE];
    __shared__ __align__(16) unsigned Bs[2][2 * PLANE];

    int tid  = threadIdx.x;
    int lane = tid & 31;
    int warp = tid >> 5;
    int wm = warp >> 1, wn = warp & 1;
    int bm = blockIdx.y * TBM;
    int bn = blockIdx.x * 128;

    int arow = tid >> 1, ah = tid & 1;
    const float* Aptr = A + (size_t)(bm + arow) * K + ah * 8;
    int xa = (arow & 3) ^ ((arow >> 3) & 3);
    int ast_base = arow * XSTR + 4 * ah;
    int bnn = tid & 127, bh2 = tid >> 7;
    int gcol = bn + bnn;
    int xb = (bnn & 3) ^ ((bnn >> 3) & 3);
    int bst_base = bnn * XSTR + 4 * bh2;

    int fg = lane >> 2, ft = lane & 3;
    int idxA[2][2];
#pragma unroll
    for (int i = 0; i < 2; i++)
#pragma unroll
        for (int d = 0; d < 2; d++) {
            int row = wm * 32 + i * 16 + d * 8 + fg;
            idxA[i][d] = row * XSTR + (ft ^ (row & 3) ^ ((row >> 3) & 3));
        }
    int idxB[8];
#pragma unroll
    for (int j = 0; j < 8; j++) {
        int n = wn * 64 + j * 8 + fg;
        idxB[j] = n * XSTR + (ft ^ (n & 3) ^ ((n >> 3) & 3));
    }

    float acc[2][8][4];
#pragma unroll
    for (int i = 0; i < 2; i++)
#pragma unroll
        for (int j = 0; j < 8; j++)
#pragma unroll
            for (int l = 0; l < 4; l++) acc[i][j][l] = 0.f;

    {
        float4 f0 = *(const float4*)Aptr;
        float4 f1 = *(const float4*)(Aptr + 4);
        unsigned hi, lo;
        split2(f0.x, f0.y, hi, lo);
        As[0][ast_base + (0 ^ xa)] = hi; As[0][PLANE + ast_base + (0 ^ xa)] = lo;
        split2(f0.z, f0.w, hi, lo);
        As[0][ast_base + (1 ^ xa)] = hi; As[0][PLANE + ast_base + (1 ^ xa)] = lo;
        split2(f1.x, f1.y, hi, lo);
        As[0][ast_base + (2 ^ xa)] = hi; As[0][PLANE + ast_base + (2 ^ xa)] = lo;
        split2(f1.z, f1.w, hi, lo);
        As[0][ast_base + (3 ^ xa)] = hi; As[0][PLANE + ast_base + (3 ^ xa)] = lo;
#pragma unroll
        for (int i = 0; i < 4; i++) {
            int k = 8 * bh2 + 2 * i;
            float b0 = (gcol < N) ? B[(size_t)k * N + gcol] : 0.f;
            float b1 = (gcol < N) ? B[(size_t)(k + 1) * N + gcol] : 0.f;
            split2(b0, b1, hi, lo);
            Bs[0][bst_base + (i ^ xb)] = hi;
            Bs[0][PLANE + bst_base + (i ^ xb)] = lo;
        }
    }
    __syncthreads();

    int iters = K / TBK;
    for (int it = 1; it <= iters; it++) {
        bool has = (it < iters);
        float4 f0, f1;
        float bg[8];
        if (has) {
            int k0 = it * TBK;
            f0 = *(const float4*)(Aptr + k0);
            f1 = *(const float4*)(Aptr + k0 + 4);
#pragma unroll
            for (int i = 0; i < 4; i++) {
                int k = k0 + 8 * bh2 + 2 * i;
                bg[2 * i]     = (gcol < N) ? B[(size_t)k * N + gcol] : 0.f;
                bg[2 * i + 1] = (gcol < N) ? B[(size_t)(k + 1) * N + gcol] : 0.f;
            }
        }
        {
            const unsigned* Ab = As[(it - 1) & 1];
            const unsigned* Bb = Bs[(it - 1) & 1];
            unsigned ahf[2][4], alf[2][4];
#pragma unroll
            for (int i = 0; i < 2; i++) {
                ahf[i][0] = Ab[idxA[i][0]];
                ahf[i][1] = Ab[idxA[i][1]];
                ahf[i][2] = Ab[idxA[i][0] + 4];
                ahf[i][3] = Ab[idxA[i][1] + 4];
                alf[i][0] = Ab[PLANE + idxA[i][0]];
                alf[i][1] = Ab[PLANE + idxA[i][1]];
                alf[i][2] = Ab[PLANE + idxA[i][0] + 4];
                alf[i][3] = Ab[PLANE + idxA[i][1] + 4];
            }
#pragma unroll
            for (int j = 0; j < 8; j++) {
                unsigned bh0 = Bb[idxB[j]];
                unsigned bh1 = Bb[idxB[j] + 4];
                unsigned bl0 = Bb[PLANE + idxB[j]];
                unsigned bl1 = Bb[PLANE + idxB[j] + 4];
                mma_bf16(acc[0][j], ahf[0], bh0, bh1);
                mma_bf16(acc[1][j], ahf[1], bh0, bh1);
                mma_bf16(acc[0][j], ahf[0], bl0, bl1);
                mma_bf16(acc[1][j], ahf[1], bl0, bl1);
                mma_bf16(acc[0][j], alf[0], bh0, bh1);
                mma_bf16(acc[1][j], alf[1], bh0, bh1);
            }
        }
        if (has) {
            int buf = it & 1;
            unsigned hi, lo;
            split2(f0.x, f0.y, hi, lo);
            As[buf][ast_base + (0 ^ xa)] = hi; As[buf][PLANE + ast_base + (0 ^ xa)] = lo;
            split2(f0.z, f0.w, hi, lo);
            As[buf][ast_base + (1 ^ xa)] = hi; As[buf][PLANE + ast_base + (1 ^ xa)] = lo;
            split2(f1.x, f1.y, hi, lo);
            As[buf][ast_base + (2 ^ xa)] = hi; As[buf][PLANE + ast_base + (2 ^ xa)] = lo;
            split2(f1.z, f1.w, hi, lo);
            As[buf][ast_base + (3 ^ xa)] = hi; As[buf][PLANE + ast_base + (3 ^ xa)] = lo;
#pragma unroll
            for (int i = 0; i < 4; i++) {
                split2(bg[2 * i], bg[2 * i + 1], hi, lo);
                Bs[buf][bst_base + (i ^ xb)] = hi;
                Bs[buf][PLANE + bst_base + (i ^ xb)] = lo;
            }
        }
        __syncthreads();
    }

#pragma unroll
    for (int i = 0; i < 2; i++) {
        int row = bm + wm * 32 + i * 16 + fg;
#pragma unroll
        for (int j = 0; j < 8; j++) {
            int col = bn + wn * 64 + j * 8 + ft * 2;
            if (col < N) {
                float b0 = bias[col], b1 = bias[col + 1];
                float v0 = acc[i][j][0] + b0;
                float v1 = acc[i][j][1] + b1;
                float v2 = acc[i][j][2] + b0;
                float v3 = acc[i][j][3] + b1;
                if (act == 1) {
                    v0 = v0 / (1.f + __expf(-v0));
                    v1 = v1 / (1.f + __expf(-v1));
                    v2 = v2 / (1.f + __expf(-v2));
                    v3 = v3 / (1.f + __expf(-v3));
                }
                *(float2*)&C[(size_t)row * N + col] = make_float2(v0, v1);
                *(float2*)&C[(size_t)(row + 8) * N + col] = make_float2(v2, v3);
            }
        }
    }
}

// ===========================================================================
// Scan v7: chunked WY, T=16.  256 blocks = bh*4 + quarter (16 rows each),
// 128 threads: rr=tid>>3 (row), g=tid&7 (8 cols).
// Per chunk: parallel matvecs (M·k_i, M·q_i), 240 Gram dots (2/thread),
// scalar forward substitution (short chain), rank-16 M update.
// Exact algebra: f_j = eta_j c0_j err_j / A_j;  A_i = prod alpha;
//   err_i = c0_i A_{i-1} (dk0_i + sum_{j<i} f_j kk[j][i]) - c1_i v_i
//   y_i   = c2_i A_{i-1} (dq0_i + sum_{j<i} f_j kq[j][i])
//   M_T   = A_T (M_0 + sum_j f_j k_j^T)
// Step stride 196 floats in smem (breaks 192 % 32 == 0 bank aliasing).
// ===========================================================================
#define CT 16
#define KSTR 196

__global__ __launch_bounds__(128) void scan_kernel(
    const float* __restrict__ base,    // [B,S,H,3,HD]
    const float* __restrict__ ctrl,    // [B,S,H,5]
    const float* __restrict__ memory0, // [B,H,HD,HD]
    float* __restrict__ ys,            // [B,S,D]
    float* __restrict__ mfinal)        // [B,H,HD,HD]
{
    __shared__ __align__(16) float kqv[2][CT * KSTR];
    __shared__ float cbuf[2][CT * 8];
    __shared__ float sc0[CT], sc1[CT], sc2[CT], seta[CT];
    __shared__ float salpha[CT], sralpha[CT];
    __shared__ float gkk[CT * CT], gkq[CT * CT];

    int bh      = blockIdx.x >> 2;
    int quarter = blockIdx.x & 3;
    int b = bh >> 4, h = bh & 15;
    int tid = threadIdx.x;
    int rr = tid >> 3;                 // 0..15
    int r  = quarter * 16 + rr;        // global row 0..63
    int g  = tid & 7;                  // column group (8 cols)

    float m[8];
    {
        const float* M0 = memory0 + (((size_t)bh * HDIM + r) * HDIM + g * 8);
#pragma unroll
        for (int jj = 0; jj < 8; jj++) m[jj] = M0[jj];
    }

    const float* bsrc = base + ((size_t)b * SS * HH + h) * 192;  // +step*3072
    const float* csrc = ctrl + (size_t)b * SS * 80 + h * 5;      // +step*80
    float* yptr = ys + (size_t)b * SS * DD + h * HDIM + r;

    // Gram pair decode (once): thread t<120 -> pair (gj, gi), gj<gi
    int gj = 0, gi = 0;
    if (tid < 120) {
        int idx = tid, j = 0;
        while (idx >= 15 - j) { idx -= 15 - j; j++; }
        gj = j; gi = j + 1 + idx;
    }

    int lst = tid >> 3;   // step this thread loads
    int lln = tid & 7;

#define CH_ISSUE(ck, bf) do {                                               \
        const float* bp_ = bsrc + (size_t)((ck) * CT + lst) * 3072;         \
        unsigned da_ = (unsigned)__cvta_generic_to_shared(                  \
                           &kqv[bf][lst * KSTR]);                           \
        _Pragma("unroll")                                                   \
        for (int i_ = 0; i_ < 6; i_++)                                      \
            cpa16(da_ + (unsigned)(lln + i_ * 8) * 16,                      \
                  bp_ + (lln + i_ * 8) * 4);                                \
        if (lln < 5)                                                        \
            cpa4((unsigned)__cvta_generic_to_shared(                        \
                     &cbuf[bf][lst * 8 + lln]),                             \
                 csrc + (size_t)((ck) * CT + lst) * 80 + lln);              \
        cpcommit();                                                         \
    } while (0)

    CH_ISSUE(0, 0);
    CH_ISSUE(1, 1);

    const int NCH = SS / CT;   // 128
    for (int c = 0; c < NCH; c++) {
        cpwait<1>();
        __syncthreads();       // chunk c data visible
        int buf = c & 1;
        const float* ch = kqv[buf];

        // per-step scalars
        if (tid < CT) {
            const float* cb = &cbuf[buf][tid * 8];
            sc0[tid] = cb[0]; sc1[tid] = cb[1]; sc2[tid] = cb[2];
            seta[tid] = 1.f / (1.f + __expf(-cb[3]));
            float ex = __expf(-cb[4]);
            float ra = 1.f + ex;           // 1/alpha
            sralpha[tid] = ra;
            salpha[tid] = 1.f / ra;        // alpha
        }

        // batched matvecs (parallel across i)
        float dk0[CT], dq0[CT];
#pragma unroll
        for (int i = 0; i < CT; i++) {
            const float* sp = ch + i * KSTR;
            float4 ka = *(const float4*)&sp[g * 8];
            float4 kb = *(const float4*)&sp[g * 8 + 4];
            float4 qa = *(const float4*)&sp[128 + g * 8];
            float4 qb = *(const float4*)&sp[128 + g * 8 + 4];
            dk0[i] = m[0]*ka.x + m[1]*ka.y + m[2]*ka.z + m[3]*ka.w
                   + m[4]*kb.x + m[5]*kb.y + m[6]*kb.z + m[7]*kb.w;
            dq0[i] = m[0]*qa.x + m[1]*qa.y + m[2]*qa.z + m[3]*qa.w
                   + m[4]*qb.x + m[5]*qb.y + m[6]*qb.z + m[7]*qb.w;
        }
#pragma unroll
        for (int d = 1; d <= 4; d <<= 1) {
#pragma unroll
            for (int i = 0; i < CT; i++) {
                dk0[i] += __shfl_xor_sync(0xffffffffu, dk0[i], d);
                dq0[i] += __shfl_xor_sync(0xffffffffu, dq0[i], d);
            }
        }

        // Gram dots (2 per thread, threads 0..119)
        if (tid < 120) {
            const float* kj = ch + gj * KSTR;
            const float* ki = ch + gi * KSTR;
            float s1 = 0.f, s2 = 0.f;
#pragma unroll
            for (int cq = 0; cq < 16; cq++) {
                float4 a  = *(const float4*)&kj[cq * 4];
                float4 bq = *(const float4*)&ki[cq * 4];
                float4 qq = *(const float4*)&ki[128 + cq * 4];
                s1 += a.x*bq.x + a.y*bq.y + a.z*bq.z + a.w*bq.w;
                s2 += a.x*qq.x + a.y*qq.y + a.z*qq.z + a.w*qq.w;
            }
            gkk[gj * CT + gi] = s1;
            gkq[gj * CT + gi] = s2;
        }
        __syncthreads();       // scalars + Gram visible

        // forward substitution (short scalar chain; rank updates off-path)
        float f[CT];
        float Acur = 1.f, rAcur = 1.f;
#pragma unroll
        for (int i = 0; i < CT; i++) {
            float vv = ch[i * KSTR + 64 + r];
            float err = sc0[i] * Acur * dk0[i] - sc1[i] * vv;
            rAcur *= sralpha[i];
            Acur  *= salpha[i];
            float fi = seta[i] * sc0[i] * err * rAcur;
            f[i] = fi;
#pragma unroll
            for (int ii = i + 1; ii < CT; ii++) {
                dk0[ii] += fi * gkk[i * CT + ii];
                dq0[ii] += fi * gkq[i * CT + ii];
            }
        }
        float A16 = Acur;

        // y writes (recompute A_{i-1} running; predicated stores)
        {
            float Ay = 1.f;
#pragma unroll
            for (int i = 0; i < CT; i++) {
                if (i == g || i == g + 8)
                    yptr[(size_t)(c * CT + i) * DD] = sc2[i] * Ay * dq0[i];
                Ay *= salpha[i];
            }
        }

        // rank-16 update of M
#pragma unroll
        for (int j = 0; j < CT; j++) {
            const float* sp = ch + j * KSTR + g * 8;
            float4 ka = *(const float4*)&sp[0];
            float4 kb = *(const float4*)&sp[4];
            float fj = f[j];
            m[0] += fj * ka.x; m[1] += fj * ka.y;
            m[2] += fj * ka.z; m[3] += fj * ka.w;
            m[4] += fj * kb.x; m[5] += fj * kb.y;
            m[6] += fj * kb.z; m[7] += fj * kb.w;
        }
#pragma unroll
        for (int jj = 0; jj < 8; jj++) m[jj] *= A16;

        __syncthreads();       // all reads of this buffer done
        if (c + 2 < NCH) CH_ISSUE(c + 2, buf);
        else cpcommit();
    }

    float* MF = mfinal + (((size_t)bh * HDIM + r) * HDIM + g * 8);
#pragma unroll
    for (int jj = 0; jj < 8; jj++) MF[jj] = m[jj];
}

// ===========================================================================
extern "C" void kernel_launch(void* const* d_in, const int* in_sizes, int n_in,
                              void* d_out, int out_size)
{
    (void)in_sizes; (void)n_in;
    const float* x       = (const float*)d_in[0];
    const float* memory0 = (const float*)d_in[1];
    const float* W_in    = (const float*)d_in[2];
    const float* b_in    = (const float*)d_in[3];
    const float* Wc1     = (const float*)d_in[4];
    const float* bc1     = (const float*)d_in[5];
    const float* Wc2     = (const float*)d_in[6];
    const float* bc2     = (const float*)d_in[7];
    const float* W_out   = (const float*)d_in[8];
    const float* b_out   = (const float*)d_in[9];

    float* out = (float*)d_out;

    float *base, *hidden, *ctrl, *ys, *mf_scratch;
    cudaGetSymbolAddress((void**)&base,       g_base);
    cudaGetSymbolAddress((void**)&hidden,     g_hidden);
    cudaGetSymbolAddress((void**)&ctrl,       g_ctrl);
    cudaGetSymbolAddress((void**)&ys,         g_ys);
    cudaGetSymbolAddress((void**)&mf_scratch, g_mf);

    const size_t OUT_ELEMS = (size_t)MR * DD;
    const size_t MF_ELEMS  = (size_t)BB * HH * HDIM * HDIM;
    float* mfinal = ((size_t)out_size >= OUT_ELEMS + MF_ELEMS)
                        ? (out + OUT_ELEMS) : mf_scratch;

    // ---- fork: ctrl path (gemm2 -> gemm3) on s2, base gemm on main ----
    cudaEventRecord(g_hx.e1, 0);
    cudaStreamWaitEvent(g_hx.s2, g_hx.e1, 0);

    gemm_bf16x3<<<dim3(DD / 128, MR / TBM), 256, 0, g_hx.s2>>>(
        x, Wc1, bc1, hidden, MR, DD, DD, 1);
    gemm_bf16x3<<<dim3(1, MR / TBM), 256, 0, g_hx.s2>>>(
        hidden, Wc2, bc2, ctrl, MR, 5 * HH, DD, 0);
    cudaEventRecord(g_hx.e2, g_hx.s2);

    gemm_bf16x3<<<dim3(3 * DD / 128, MR / TBM), 256>>>(
        x, W_in, b_in, base, MR, 3 * DD, DD, 0);

    // ---- join: scan needs base (main) + ctrl (s2) ----
    cudaStreamWaitEvent((cudaStream_t)0, g_hx.e2, 0);

    // chunked-WY scan
    scan_kernel<<<BB * HH * 4, 128>>>(base, ctrl, memory0, ys, mfinal);
    // out = ys @ W_out + b_out
    gemm_bf16x3<<<dim3(DD / 128, MR / TBM), 256>>>(
        ys, W_out, b_out, out, MR, DD, DD, 0);
}